// round 2
// baseline (speedup 1.0000x reference)
#include <cuda_runtime.h>
#include <math.h>

#define BD   256          // threads per block
#define NW   8            // warps per block
#define DD   128          // embed dim
#define K1   160          // embed + temporal
#define TD   32           // temporal dim

__device__ __forceinline__ float4 ld4(const float* p) { return *(const float4*)p; }

__device__ __forceinline__ void fma4(float4& a, float s, const float4& w) {
    a.x = fmaf(s, w.x, a.x);
    a.y = fmaf(s, w.y, a.y);
    a.z = fmaf(s, w.z, a.z);
    a.w = fmaf(s, w.w, a.w);
}

__device__ __forceinline__ float gelu_exact(float x) {
    return 0.5f * x * (1.0f + erff(x * 0.70710678118654752f));
}

__global__ __launch_bounds__(BD, 1)
void tee_kernel(const int*   __restrict__ ids,
                const float* __restrict__ dates,
                const int*   __restrict__ lengths,
                const float* __restrict__ emb,
                const float* __restrict__ tp_w,  const float* __restrict__ tp_b,
                const float* __restrict__ tp_lnw, const float* __restrict__ tp_lnb,
                const float* __restrict__ w1, const float* __restrict__ b1,
                const float* __restrict__ ln1w, const float* __restrict__ ln1b,
                const float* __restrict__ w2, const float* __restrict__ b2,
                const float* __restrict__ ln2w, const float* __restrict__ ln2b,
                float* __restrict__ out, int B, int L)
{
    extern __shared__ float smem[];
    float* sw1   = smem;                      // 160*128
    float* sw2   = sw1 + K1 * DD;             // 128*128
    float* sxb   = sw2 + DD * DD;             // NW * 4 * 160
    float* spart = sxb + NW * 4 * K1;         // NW * 128

    const int b    = blockIdx.x;
    const int tid  = threadIdx.x;
    const int warp = tid >> 5;
    const int lane = tid & 31;
    const int f4   = lane * 4;

    // Stage weights into SMEM (L2-resident after first wave).
    for (int i = tid; i < K1 * DD; i += BD) sw1[i] = w1[i];
    for (int i = tid; i < DD * DD; i += BD) sw2[i] = w2[i];
    __syncthreads();

    const int len = lengths[b];

    // Per-lane parameters (features f4..f4+3).
    const float4 bf1 = ld4(b1 + f4), l1w = ld4(ln1w + f4), l1b = ld4(ln1b + f4);
    const float4 bf2 = ld4(b2 + f4), l2w = ld4(ln2w + f4), l2b = ld4(ln2b + f4);
    const float tpw = tp_w[lane], tpb = tp_b[lane];
    const float tplw = tp_lnw[lane], tplb = tp_lnb[lane];

    float4 pool = make_float4(0.f, 0.f, 0.f, 0.f);
    float* xw = sxb + warp * (4 * K1);

    const int ngroups = (len + 3) >> 2;   // groups of 4 tokens; masked tokens skipped
    for (int gi = warp; gi < ngroups; gi += NW) {
        const int l0 = gi * 4;

        // ---- stage inputs: emb gather + temporal branch (Linear->LN->GELU) ----
        #pragma unroll
        for (int t = 0; t < 4; t++) {
            int l = l0 + t; if (l >= L) l = L - 1;   // clamp; inactive tokens not pooled
            const int id = ids[b * L + l];
            const float* er = emb + id * DD;
            xw[t * K1 + lane]      = er[lane];
            xw[t * K1 + lane + 32] = er[lane + 32];
            xw[t * K1 + lane + 64] = er[lane + 64];
            xw[t * K1 + lane + 96] = er[lane + 96];

            const float dn = dates[b * L + l] * (1.0f / 1825.0f);
            const float v  = fmaf(dn, tpw, tpb);
            float s = v, sq = v * v;
            #pragma unroll
            for (int o = 16; o; o >>= 1) {
                s  += __shfl_xor_sync(0xffffffffu, s,  o);
                sq += __shfl_xor_sync(0xffffffffu, sq, o);
            }
            const float m   = s * (1.0f / TD);
            const float var = sq * (1.0f / TD) - m * m;
            const float rs  = rsqrtf(var + 1e-5f);
            const float u   = (v - m) * rs * tplw + tplb;
            xw[t * K1 + DD + lane] = gelu_exact(u);
        }
        __syncwarp();

        // ---- mm1: [4 tokens x 160] @ [160 x 128] ----
        float4 acc[4];
        #pragma unroll
        for (int t = 0; t < 4; t++) acc[t] = make_float4(0.f, 0.f, 0.f, 0.f);

        for (int k = 0; k < K1; k += 4) {
            const float4 wr0 = ld4(sw1 + (k + 0) * DD + f4);
            const float4 wr1 = ld4(sw1 + (k + 1) * DD + f4);
            const float4 wr2 = ld4(sw1 + (k + 2) * DD + f4);
            const float4 wr3 = ld4(sw1 + (k + 3) * DD + f4);
            #pragma unroll
            for (int t = 0; t < 4; t++) {
                const float4 xv = ld4(xw + t * K1 + k);
                fma4(acc[t], xv.x, wr0);
                fma4(acc[t], xv.y, wr1);
                fma4(acc[t], xv.z, wr2);
                fma4(acc[t], xv.w, wr3);
            }
        }

        // ---- LN1 + GELU, write activations back for mm2 ----
        #pragma unroll
        for (int t = 0; t < 4; t++) {
            float4 y = acc[t];
            y.x += bf1.x; y.y += bf1.y; y.z += bf1.z; y.w += bf1.w;
            float s  = y.x + y.y + y.z + y.w;
            float sq = y.x * y.x + y.y * y.y + y.z * y.z + y.w * y.w;
            #pragma unroll
            for (int o = 16; o; o >>= 1) {
                s  += __shfl_xor_sync(0xffffffffu, s,  o);
                sq += __shfl_xor_sync(0xffffffffu, sq, o);
            }
            const float m   = s * (1.0f / DD);
            const float var = sq * (1.0f / DD) - m * m;
            const float rs  = rsqrtf(var + 1e-5f);
            float4 g;
            g.x = gelu_exact((y.x - m) * rs * l1w.x + l1b.x);
            g.y = gelu_exact((y.y - m) * rs * l1w.y + l1b.y);
            g.z = gelu_exact((y.z - m) * rs * l1w.z + l1b.z);
            g.w = gelu_exact((y.w - m) * rs * l1w.w + l1b.w);
            *(float4*)(xw + t * K1 + f4) = g;
        }
        __syncwarp();

        // ---- mm2: [4 tokens x 128] @ [128 x 128] ----
        #pragma unroll
        for (int t = 0; t < 4; t++) acc[t] = make_float4(0.f, 0.f, 0.f, 0.f);

        for (int k = 0; k < DD; k += 4) {
            const float4 wr0 = ld4(sw2 + (k + 0) * DD + f4);
            const float4 wr1 = ld4(sw2 + (k + 1) * DD + f4);
            const float4 wr2 = ld4(sw2 + (k + 2) * DD + f4);
            const float4 wr3 = ld4(sw2 + (k + 3) * DD + f4);
            #pragma unroll
            for (int t = 0; t < 4; t++) {
                const float4 xv = ld4(xw + t * K1 + k);
                fma4(acc[t], xv.x, wr0);
                fma4(acc[t], xv.y, wr1);
                fma4(acc[t], xv.z, wr2);
                fma4(acc[t], xv.w, wr3);
            }
        }

        // ---- LN2 + masked pooling ----
        #pragma unroll
        for (int t = 0; t < 4; t++) {
            float4 y = acc[t];
            y.x += bf2.x; y.y += bf2.y; y.z += bf2.z; y.w += bf2.w;
            float s  = y.x + y.y + y.z + y.w;
            float sq = y.x * y.x + y.y * y.y + y.z * y.z + y.w * y.w;
            #pragma unroll
            for (int o = 16; o; o >>= 1) {
                s  += __shfl_xor_sync(0xffffffffu, s,  o);
                sq += __shfl_xor_sync(0xffffffffu, sq, o);
            }
            const float m   = s * (1.0f / DD);
            const float var = sq * (1.0f / DD) - m * m;
            const float rs  = rsqrtf(var + 1e-5f);
            if (l0 + t < len) {
                pool.x += (y.x - m) * rs * l2w.x + l2b.x;
                pool.y += (y.y - m) * rs * l2w.y + l2b.y;
                pool.z += (y.z - m) * rs * l2w.z + l2b.z;
                pool.w += (y.w - m) * rs * l2w.w + l2b.w;
            }
        }
        __syncwarp();
    }

    // ---- cross-warp pooling reduction ----
    *(float4*)(spart + warp * DD + f4) = pool;
    __syncthreads();

    if (tid < DD) {
        float s = 0.f;
        #pragma unroll
        for (int w = 0; w < NW; w++) s += spart[w * DD + tid];
        out[b * DD + tid] = (len > 0) ? s / (float)len : 0.0f;
    }
}

extern "C" void kernel_launch(void* const* d_in, const int* in_sizes, int n_in,
                              void* d_out, int out_size)
{
    const int*   ids     = (const int*)  d_in[0];
    const float* dates   = (const float*)d_in[1];
    const int*   lengths = (const int*)  d_in[2];
    const float* emb     = (const float*)d_in[3];
    const float* tp_w    = (const float*)d_in[4];
    const float* tp_b    = (const float*)d_in[5];
    const float* tp_lnw  = (const float*)d_in[6];
    const float* tp_lnb  = (const float*)d_in[7];
    const float* w1      = (const float*)d_in[8];
    const float* b1      = (const float*)d_in[9];
    const float* ln1w    = (const float*)d_in[10];
    const float* ln1b    = (const float*)d_in[11];
    const float* w2      = (const float*)d_in[12];
    const float* b2      = (const float*)d_in[13];
    const float* ln2w    = (const float*)d_in[14];
    const float* ln2b    = (const float*)d_in[15];
    float* out = (float*)d_out;

    const int B = in_sizes[2];            // 4096
    const int L = in_sizes[0] / B;        // 200

    const size_t smem_bytes = (size_t)(K1 * DD + DD * DD + NW * 4 * K1 + NW * DD) * sizeof(float);
    cudaFuncSetAttribute(tee_kernel, cudaFuncAttributeMaxDynamicSharedMemorySize, (int)smem_bytes);

    tee_kernel<<<B, BD, smem_bytes>>>(ids, dates, lengths, emb,
                                      tp_w, tp_b, tp_lnw, tp_lnb,
                                      w1, b1, ln1w, ln1b,
                                      w2, b2, ln2w, ln2b,
                                      out, B, L);
}

// round 5
// speedup vs baseline: 1.1660x; 1.1660x over previous
#include <cuda_runtime.h>
#include <math.h>

#define BD   256          // threads per block
#define NW   8            // warps per block
#define DD   128          // embed dim
#define K1   160          // embed + temporal
#define TD   32           // temporal dim
#define TOK  8            // tokens per warp group

typedef unsigned long long ull;

__device__ __forceinline__ float4 ld4(const float* p) { return *(const float4*)p; }

// packed fp32x2 fma: acc = w * x + acc   (sm_103a; ptxas never auto-fuses this)
#define FMA2(acc, w, x) asm("fma.rn.f32x2 %0, %1, %2, %0;" : "+l"(acc) : "l"(w), "l"(x))

__device__ __forceinline__ ull splat2(float v) {
    ull r; unsigned int u = __float_as_uint(v);
    asm("mov.b64 %0, {%1, %2};" : "=l"(r) : "r"(u), "r"(u));
    return r;
}
__device__ __forceinline__ void unpack2(ull p, float& lo, float& hi) {
    unsigned int a, b;
    asm("mov.b64 {%0, %1}, %2;" : "=r"(a), "=r"(b) : "l"(p));
    lo = __uint_as_float(a); hi = __uint_as_float(b);
}

__device__ __forceinline__ float gelu_exact(float x) {
    return 0.5f * x * (1.0f + erff(x * 0.70710678118654752f));
}

struct P2 { ull a, b; };   // 4 fp32 accumulators as 2 packed pairs

__global__ __launch_bounds__(BD, 1)
void tee_kernel(const int*   __restrict__ ids,
                const float* __restrict__ dates,
                const int*   __restrict__ lengths,
                const float* __restrict__ emb,
                const float* __restrict__ tp_w,  const float* __restrict__ tp_b,
                const float* __restrict__ tp_lnw, const float* __restrict__ tp_lnb,
                const float* __restrict__ w1, const float* __restrict__ b1,
                const float* __restrict__ ln1w, const float* __restrict__ ln1b,
                const float* __restrict__ w2, const float* __restrict__ b2,
                const float* __restrict__ ln2w, const float* __restrict__ ln2b,
                float* __restrict__ out, int B, int L)
{
    extern __shared__ float smem[];
    float* sw1   = smem;                      // 160*128  (80 KB)
    float* sw2   = sw1 + K1 * DD;             // 128*128  (64 KB)
    float* sxb   = sw2 + DD * DD;             // NW * TOK * 160 (40 KB)
    float* spart = sxb + NW * TOK * K1;       // NW * 128 (4 KB)

    const int b    = blockIdx.x;
    const int tid  = threadIdx.x;
    const int warp = tid >> 5;
    const int lane = tid & 31;
    const int f4   = lane * 4;

    for (int i = tid; i < K1 * DD; i += BD) sw1[i] = w1[i];
    for (int i = tid; i < DD * DD; i += BD) sw2[i] = w2[i];
    __syncthreads();

    const int len = lengths[b];

    const float4 bf1 = ld4(b1 + f4), l1w = ld4(ln1w + f4), l1b = ld4(ln1b + f4);
    const float4 bf2 = ld4(b2 + f4), l2w = ld4(ln2w + f4), l2b = ld4(ln2b + f4);
    const float tpw = tp_w[lane], tpb = tp_b[lane];
    const float tplw = tp_lnw[lane], tplb = tp_lnb[lane];

    float4 pool = make_float4(0.f, 0.f, 0.f, 0.f);
    float* xw = sxb + warp * (TOK * K1);

    const int ngroups = (len + TOK - 1) / TOK;   // masked tokens skipped
    for (int gi = warp; gi < ngroups; gi += NW) {
        const int l0 = gi * TOK;

        // ---- stage inputs: emb gather + temporal branch (Linear->LN->GELU) ----
        #pragma unroll
        for (int t = 0; t < TOK; t++) {
            int l = l0 + t; if (l >= L) l = L - 1;   // clamp; inactive tokens not pooled
            const int id = ids[b * L + l];
            const float* er = emb + id * DD;
            xw[t * K1 + lane]      = er[lane];
            xw[t * K1 + lane + 32] = er[lane + 32];
            xw[t * K1 + lane + 64] = er[lane + 64];
            xw[t * K1 + lane + 96] = er[lane + 96];

            const float dn = dates[b * L + l] * (1.0f / 1825.0f);
            const float v  = fmaf(dn, tpw, tpb);
            float s = v, sq = v * v;
            #pragma unroll
            for (int o = 16; o; o >>= 1) {
                s  += __shfl_xor_sync(0xffffffffu, s,  o);
                sq += __shfl_xor_sync(0xffffffffu, sq, o);
            }
            const float m   = s * (1.0f / TD);
            const float var = sq * (1.0f / TD) - m * m;
            const float rs  = rsqrtf(var + 1e-5f);
            const float u   = (v - m) * rs * tplw + tplb;
            xw[t * K1 + DD + lane] = gelu_exact(u);
        }
        __syncwarp();

        // ---- mm1: [TOK x 160] @ [160 x 128], packed f32x2 ----
        P2 acc[TOK];
        #pragma unroll
        for (int t = 0; t < TOK; t++) { acc[t].a = 0ull; acc[t].b = 0ull; }

        for (int k = 0; k < K1; k += 4) {
            const ulonglong2 w0 = *(const ulonglong2*)(sw1 + (k + 0) * DD + f4);
            const ulonglong2 w1r= *(const ulonglong2*)(sw1 + (k + 1) * DD + f4);
            const ulonglong2 w2r= *(const ulonglong2*)(sw1 + (k + 2) * DD + f4);
            const ulonglong2 w3r= *(const ulonglong2*)(sw1 + (k + 3) * DD + f4);
            #pragma unroll
            for (int t = 0; t < TOK; t++) {
                const float4 xv = ld4(xw + t * K1 + k);
                const ull x0 = splat2(xv.x), x1 = splat2(xv.y);
                const ull x2 = splat2(xv.z), x3 = splat2(xv.w);
                FMA2(acc[t].a, w0.x, x0);  FMA2(acc[t].b, w0.y, x0);
                FMA2(acc[t].a, w1r.x, x1); FMA2(acc[t].b, w1r.y, x1);
                FMA2(acc[t].a, w2r.x, x2); FMA2(acc[t].b, w2r.y, x2);
                FMA2(acc[t].a, w3r.x, x3); FMA2(acc[t].b, w3r.y, x3);
            }
        }

        // ---- LN1 + GELU, write activations back for mm2 ----
        #pragma unroll
        for (int t = 0; t < TOK; t++) {
            float4 y;
            unpack2(acc[t].a, y.x, y.y);
            unpack2(acc[t].b, y.z, y.w);
            y.x += bf1.x; y.y += bf1.y; y.z += bf1.z; y.w += bf1.w;
            float s  = y.x + y.y + y.z + y.w;
            float sq = y.x * y.x + y.y * y.y + y.z * y.z + y.w * y.w;
            #pragma unroll
            for (int o = 16; o; o >>= 1) {
                s  += __shfl_xor_sync(0xffffffffu, s,  o);
                sq += __shfl_xor_sync(0xffffffffu, sq, o);
            }
            const float m   = s * (1.0f / DD);
            const float var = sq * (1.0f / DD) - m * m;
            const float rs  = rsqrtf(var + 1e-5f);
            float4 g;
            g.x = gelu_exact((y.x - m) * rs * l1w.x + l1b.x);
            g.y = gelu_exact((y.y - m) * rs * l1w.y + l1b.y);
            g.z = gelu_exact((y.z - m) * rs * l1w.z + l1b.z);
            g.w = gelu_exact((y.w - m) * rs * l1w.w + l1b.w);
            *(float4*)(xw + t * K1 + f4) = g;
        }
        __syncwarp();

        // ---- mm2: [TOK x 128] @ [128 x 128], packed f32x2 ----
        #pragma unroll
        for (int t = 0; t < TOK; t++) { acc[t].a = 0ull; acc[t].b = 0ull; }

        for (int k = 0; k < DD; k += 4) {
            const ulonglong2 w0 = *(const ulonglong2*)(sw2 + (k + 0) * DD + f4);
            const ulonglong2 w1r= *(const ulonglong2*)(sw2 + (k + 1) * DD + f4);
            const ulonglong2 w2r= *(const ulonglong2*)(sw2 + (k + 2) * DD + f4);
            const ulonglong2 w3r= *(const ulonglong2*)(sw2 + (k + 3) * DD + f4);
            #pragma unroll
            for (int t = 0; t < TOK; t++) {
                const float4 xv = ld4(xw + t * K1 + k);
                const ull x0 = splat2(xv.x), x1 = splat2(xv.y);
                const ull x2 = splat2(xv.z), x3 = splat2(xv.w);
                FMA2(acc[t].a, w0.x, x0);  FMA2(acc[t].b, w0.y, x0);
                FMA2(acc[t].a, w1r.x, x1); FMA2(acc[t].b, w1r.y, x1);
                FMA2(acc[t].a, w2r.x, x2); FMA2(acc[t].b, w2r.y, x2);
                FMA2(acc[t].a, w3r.x, x3); FMA2(acc[t].b, w3r.y, x3);
            }
        }

        // ---- LN2 + masked pooling ----
        #pragma unroll
        for (int t = 0; t < TOK; t++) {
            float4 y;
            unpack2(acc[t].a, y.x, y.y);
            unpack2(acc[t].b, y.z, y.w);
            y.x += bf2.x; y.y += bf2.y; y.z += bf2.z; y.w += bf2.w;
            float s  = y.x + y.y + y.z + y.w;
            float sq = y.x * y.x + y.y * y.y + y.z * y.z + y.w * y.w;
            #pragma unroll
            for (int o = 16; o; o >>= 1) {
                s  += __shfl_xor_sync(0xffffffffu, s,  o);
                sq += __shfl_xor_sync(0xffffffffu, sq, o);
            }
            const float m   = s * (1.0f / DD);
            const float var = sq * (1.0f / DD) - m * m;
            const float rs  = rsqrtf(var + 1e-5f);
            if (l0 + t < len) {
                pool.x += (y.x - m) * rs * l2w.x + l2b.x;
                pool.y += (y.y - m) * rs * l2w.y + l2b.y;
                pool.z += (y.z - m) * rs * l2w.z + l2b.z;
                pool.w += (y.w - m) * rs * l2w.w + l2b.w;
            }
        }
        __syncwarp();
    }

    // ---- cross-warp pooling reduction ----
    *(float4*)(spart + warp * DD + f4) = pool;
    __syncthreads();

    if (tid < DD) {
        float s = 0.f;
        #pragma unroll
        for (int w = 0; w < NW; w++) s += spart[w * DD + tid];
        out[b * DD + tid] = (len > 0) ? s / (float)len : 0.0f;
    }
}

extern "C" void kernel_launch(void* const* d_in, const int* in_sizes, int n_in,
                              void* d_out, int out_size)
{
    const int*   ids     = (const int*)  d_in[0];
    const float* dates   = (const float*)d_in[1];
    const int*   lengths = (const int*)  d_in[2];
    const float* emb     = (const float*)d_in[3];
    const float* tp_w    = (const float*)d_in[4];
    const float* tp_b    = (const float*)d_in[5];
    const float* tp_lnw  = (const float*)d_in[6];
    const float* tp_lnb  = (const float*)d_in[7];
    const float* w1      = (const float*)d_in[8];
    const float* b1      = (const float*)d_in[9];
    const float* ln1w    = (const float*)d_in[10];
    const float* ln1b    = (const float*)d_in[11];
    const float* w2      = (const float*)d_in[12];
    const float* b2      = (const float*)d_in[13];
    const float* ln2w    = (const float*)d_in[14];
    const float* ln2b    = (const float*)d_in[15];
    float* out = (float*)d_out;

    const int B = in_sizes[2];            // 4096
    const int L = in_sizes[0] / B;        // 200

    const size_t smem_bytes = (size_t)(K1 * DD + DD * DD + NW * TOK * K1 + NW * DD) * sizeof(float);
    cudaFuncSetAttribute(tee_kernel, cudaFuncAttributeMaxDynamicSharedMemorySize, (int)smem_bytes);

    tee_kernel<<<B, BD, smem_bytes>>>(ids, dates, lengths, emb,
                                      tp_w, tp_b, tp_lnw, tp_lnb,
                                      w1, b1, ln1w, ln1b,
                                      w2, b2, ln2w, ln2b,
                                      out, B, L);
}

// round 6
// speedup vs baseline: 1.2668x; 1.0864x over previous
#include <cuda_runtime.h>
#include <math.h>

#define BD   384          // threads per block
#define NW   12           // warps per block (3 per SMSP)
#define DD   128          // embed dim
#define K1   160          // embed + temporal
#define TD   32           // temporal dim
#define TOK  8            // tokens per warp group

typedef unsigned long long ull;

__device__ __forceinline__ float4 ld4(const float* p) { return *(const float4*)p; }

// packed fp32x2 fma: acc = w * x + acc   (sm_103a; ptxas never auto-fuses this)
#define FMA2(acc, w, x) asm("fma.rn.f32x2 %0, %1, %2, %0;" : "+l"(acc) : "l"(w), "l"(x))

__device__ __forceinline__ ull splat2(float v) {
    ull r; unsigned int u = __float_as_uint(v);
    asm("mov.b64 %0, {%1, %2};" : "=l"(r) : "r"(u), "r"(u));
    return r;
}
__device__ __forceinline__ void unpack2(ull p, float& lo, float& hi) {
    unsigned int a, b;
    asm("mov.b64 {%0, %1}, %2;" : "=r"(a), "=r"(b) : "l"(p));
    lo = __uint_as_float(a); hi = __uint_as_float(b);
}

__device__ __forceinline__ float gelu_exact(float x) {
    return 0.5f * x * (1.0f + erff(x * 0.70710678118654752f));
}

struct P2 { ull a, b; };   // 4 fp32 accumulators as 2 packed pairs

__global__ __launch_bounds__(BD, 1)
void tee_kernel(const int*   __restrict__ ids,
                const float* __restrict__ dates,
                const int*   __restrict__ lengths,
                const float* __restrict__ emb,
                const float* __restrict__ tp_w,  const float* __restrict__ tp_b,
                const float* __restrict__ tp_lnw, const float* __restrict__ tp_lnb,
                const float* __restrict__ w1, const float* __restrict__ b1,
                const float* __restrict__ ln1w, const float* __restrict__ ln1b,
                const float* __restrict__ w2, const float* __restrict__ b2,
                const float* __restrict__ ln2w, const float* __restrict__ ln2b,
                float* __restrict__ out, int B, int L)
{
    extern __shared__ float smem[];
    float* sw1   = smem;                      // 160*128  (80 KB)
    float* sw2   = sw1 + K1 * DD;             // 128*128  (64 KB)
    float* sxb   = sw2 + DD * DD;             // NW * TOK * 160 (60 KB)
    float* spart = sxb + NW * TOK * K1;       // NW * 128 (6 KB)

    const int b    = blockIdx.x;
    const int tid  = threadIdx.x;
    const int warp = tid >> 5;
    const int lane = tid & 31;
    const int f4   = lane * 4;

    for (int i = tid; i < K1 * DD; i += BD) sw1[i] = w1[i];
    for (int i = tid; i < DD * DD; i += BD) sw2[i] = w2[i];
    __syncthreads();

    const int len = lengths[b];

    const float4 bf1 = ld4(b1 + f4), l1w = ld4(ln1w + f4), l1b = ld4(ln1b + f4);
    const float4 bf2 = ld4(b2 + f4), l2w = ld4(ln2w + f4), l2b = ld4(ln2b + f4);
    const float tpw = tp_w[lane], tpb = tp_b[lane];
    const float tplw = tp_lnw[lane], tplb = tp_lnb[lane];

    float4 pool = make_float4(0.f, 0.f, 0.f, 0.f);
    float* xw = sxb + warp * (TOK * K1);

    const int ngroups = (len + TOK - 1) / TOK;   // masked tokens skipped
    for (int gi = warp; gi < ngroups; gi += NW) {
        const int l0 = gi * TOK;

        // ---- stage inputs: emb gather + temporal branch (Linear->LN->GELU) ----
        #pragma unroll
        for (int t = 0; t < TOK; t++) {
            int l = l0 + t; if (l >= L) l = L - 1;   // clamp; inactive tokens not pooled
            const int id = ids[b * L + l];
            const float* er = emb + id * DD;
            xw[t * K1 + lane]      = er[lane];
            xw[t * K1 + lane + 32] = er[lane + 32];
            xw[t * K1 + lane + 64] = er[lane + 64];
            xw[t * K1 + lane + 96] = er[lane + 96];

            const float dn = dates[b * L + l] * (1.0f / 1825.0f);
            const float v  = fmaf(dn, tpw, tpb);
            float s = v, sq = v * v;
            #pragma unroll
            for (int o = 16; o; o >>= 1) {
                s  += __shfl_xor_sync(0xffffffffu, s,  o);
                sq += __shfl_xor_sync(0xffffffffu, sq, o);
            }
            const float m   = s * (1.0f / TD);
            const float var = sq * (1.0f / TD) - m * m;
            const float rs  = rsqrtf(var + 1e-5f);
            const float u   = (v - m) * rs * tplw + tplb;
            xw[t * K1 + DD + lane] = gelu_exact(u);
        }
        __syncwarp();

        // ---- mm1: [TOK x 160] @ [160 x 128], packed f32x2 ----
        P2 acc[TOK];
        #pragma unroll
        for (int t = 0; t < TOK; t++) { acc[t].a = 0ull; acc[t].b = 0ull; }

        #pragma unroll 2
        for (int k = 0; k < K1; k += 4) {
            const ulonglong2 w0 = *(const ulonglong2*)(sw1 + (k + 0) * DD + f4);
            const ulonglong2 w1r= *(const ulonglong2*)(sw1 + (k + 1) * DD + f4);
            const ulonglong2 w2r= *(const ulonglong2*)(sw1 + (k + 2) * DD + f4);
            const ulonglong2 w3r= *(const ulonglong2*)(sw1 + (k + 3) * DD + f4);
            #pragma unroll
            for (int t = 0; t < TOK; t++) {
                const float4 xv = ld4(xw + t * K1 + k);
                const ull x0 = splat2(xv.x), x1 = splat2(xv.y);
                const ull x2 = splat2(xv.z), x3 = splat2(xv.w);
                FMA2(acc[t].a, w0.x, x0);  FMA2(acc[t].b, w0.y, x0);
                FMA2(acc[t].a, w1r.x, x1); FMA2(acc[t].b, w1r.y, x1);
                FMA2(acc[t].a, w2r.x, x2); FMA2(acc[t].b, w2r.y, x2);
                FMA2(acc[t].a, w3r.x, x3); FMA2(acc[t].b, w3r.y, x3);
            }
        }

        // ---- LN1 + GELU, write activations back for mm2 ----
        #pragma unroll
        for (int t = 0; t < TOK; t++) {
            float4 y;
            unpack2(acc[t].a, y.x, y.y);
            unpack2(acc[t].b, y.z, y.w);
            y.x += bf1.x; y.y += bf1.y; y.z += bf1.z; y.w += bf1.w;
            float s  = y.x + y.y + y.z + y.w;
            float sq = y.x * y.x + y.y * y.y + y.z * y.z + y.w * y.w;
            #pragma unroll
            for (int o = 16; o; o >>= 1) {
                s  += __shfl_xor_sync(0xffffffffu, s,  o);
                sq += __shfl_xor_sync(0xffffffffu, sq, o);
            }
            const float m   = s * (1.0f / DD);
            const float var = sq * (1.0f / DD) - m * m;
            const float rs  = rsqrtf(var + 1e-5f);
            float4 g;
            g.x = gelu_exact((y.x - m) * rs * l1w.x + l1b.x);
            g.y = gelu_exact((y.y - m) * rs * l1w.y + l1b.y);
            g.z = gelu_exact((y.z - m) * rs * l1w.z + l1b.z);
            g.w = gelu_exact((y.w - m) * rs * l1w.w + l1b.w);
            *(float4*)(xw + t * K1 + f4) = g;
        }
        __syncwarp();

        // ---- mm2: [TOK x 128] @ [128 x 128], packed f32x2 ----
        #pragma unroll
        for (int t = 0; t < TOK; t++) { acc[t].a = 0ull; acc[t].b = 0ull; }

        #pragma unroll 2
        for (int k = 0; k < DD; k += 4) {
            const ulonglong2 w0 = *(const ulonglong2*)(sw2 + (k + 0) * DD + f4);
            const ulonglong2 w1r= *(const ulonglong2*)(sw2 + (k + 1) * DD + f4);
            const ulonglong2 w2r= *(const ulonglong2*)(sw2 + (k + 2) * DD + f4);
            const ulonglong2 w3r= *(const ulonglong2*)(sw2 + (k + 3) * DD + f4);
            #pragma unroll
            for (int t = 0; t < TOK; t++) {
                const float4 xv = ld4(xw + t * K1 + k);
                const ull x0 = splat2(xv.x), x1 = splat2(xv.y);
                const ull x2 = splat2(xv.z), x3 = splat2(xv.w);
                FMA2(acc[t].a, w0.x, x0);  FMA2(acc[t].b, w0.y, x0);
                FMA2(acc[t].a, w1r.x, x1); FMA2(acc[t].b, w1r.y, x1);
                FMA2(acc[t].a, w2r.x, x2); FMA2(acc[t].b, w2r.y, x2);
                FMA2(acc[t].a, w3r.x, x3); FMA2(acc[t].b, w3r.y, x3);
            }
        }

        // ---- LN2 + masked pooling ----
        #pragma unroll
        for (int t = 0; t < TOK; t++) {
            float4 y;
            unpack2(acc[t].a, y.x, y.y);
            unpack2(acc[t].b, y.z, y.w);
            y.x += bf2.x; y.y += bf2.y; y.z += bf2.z; y.w += bf2.w;
            float s  = y.x + y.y + y.z + y.w;
            float sq = y.x * y.x + y.y * y.y + y.z * y.z + y.w * y.w;
            #pragma unroll
            for (int o = 16; o; o >>= 1) {
                s  += __shfl_xor_sync(0xffffffffu, s,  o);
                sq += __shfl_xor_sync(0xffffffffu, sq, o);
            }
            const float m   = s * (1.0f / DD);
            const float var = sq * (1.0f / DD) - m * m;
            const float rs  = rsqrtf(var + 1e-5f);
            if (l0 + t < len) {
                pool.x += (y.x - m) * rs * l2w.x + l2b.x;
                pool.y += (y.y - m) * rs * l2w.y + l2b.y;
                pool.z += (y.z - m) * rs * l2w.z + l2b.z;
                pool.w += (y.w - m) * rs * l2w.w + l2b.w;
            }
        }
        __syncwarp();
    }

    // ---- cross-warp pooling reduction ----
    *(float4*)(spart + warp * DD + f4) = pool;
    __syncthreads();

    if (tid < DD) {
        float s = 0.f;
        #pragma unroll
        for (int w = 0; w < NW; w++) s += spart[w * DD + tid];
        out[b * DD + tid] = (len > 0) ? s / (float)len : 0.0f;
    }
}

extern "C" void kernel_launch(void* const* d_in, const int* in_sizes, int n_in,
                              void* d_out, int out_size)
{
    const int*   ids     = (const int*)  d_in[0];
    const float* dates   = (const float*)d_in[1];
    const int*   lengths = (const int*)  d_in[2];
    const float* emb     = (const float*)d_in[3];
    const float* tp_w    = (const float*)d_in[4];
    const float* tp_b    = (const float*)d_in[5];
    const float* tp_lnw  = (const float*)d_in[6];
    const float* tp_lnb  = (const float*)d_in[7];
    const float* w1      = (const float*)d_in[8];
    const float* b1      = (const float*)d_in[9];
    const float* ln1w    = (const float*)d_in[10];
    const float* ln1b    = (const float*)d_in[11];
    const float* w2      = (const float*)d_in[12];
    const float* b2      = (const float*)d_in[13];
    const float* ln2w    = (const float*)d_in[14];
    const float* ln2b    = (const float*)d_in[15];
    float* out = (float*)d_out;

    const int B = in_sizes[2];            // 4096
    const int L = in_sizes[0] / B;        // 200

    const size_t smem_bytes = (size_t)(K1 * DD + DD * DD + NW * TOK * K1 + NW * DD) * sizeof(float);
    cudaFuncSetAttribute(tee_kernel, cudaFuncAttributeMaxDynamicSharedMemorySize, (int)smem_bytes);

    tee_kernel<<<B, BD, smem_bytes>>>(ids, dates, lengths, emb,
                                      tp_w, tp_b, tp_lnw, tp_lnb,
                                      w1, b1, ln1w, ln1b,
                                      w2, b2, ln2w, ln2b,
                                      out, B, L);
}

// round 9
// speedup vs baseline: 1.2893x; 1.0178x over previous
#include <cuda_runtime.h>
#include <math.h>

#define BD   512          // threads per block
#define NW   16           // warps per block (4 per SMSP)
#define DD   128          // embed dim
#define K1   160          // embed + temporal
#define TD   32           // temporal dim
#define TOK  8            // tokens per warp group

typedef unsigned long long ull;

__device__ __forceinline__ float4 ld4(const float* p) { return *(const float4*)p; }

// packed fp32x2 fma: acc = w * x + acc   (sm_103a; ptxas never auto-fuses this)
#define FMA2(acc, w, x) asm("fma.rn.f32x2 %0, %1, %2, %0;" : "+l"(acc) : "l"(w), "l"(x))

__device__ __forceinline__ ull splat2(float v) {
    ull r; unsigned int u = __float_as_uint(v);
    asm("mov.b64 %0, {%1, %2};" : "=l"(r) : "r"(u), "r"(u));
    return r;
}
__device__ __forceinline__ void unpack2(ull p, float& lo, float& hi) {
    unsigned int a, b;
    asm("mov.b64 {%0, %1}, %2;" : "=r"(a), "=r"(b) : "l"(p));
    lo = __uint_as_float(a); hi = __uint_as_float(b);
}

// two-value butterfly warp sum (shfl; redux.f32 not supported on sm_103)
__device__ __forceinline__ void warp_sum2(float& s, float& sq) {
    #pragma unroll
    for (int o = 16; o; o >>= 1) {
        s  += __shfl_xor_sync(0xffffffffu, s,  o);
        sq += __shfl_xor_sync(0xffffffffu, sq, o);
    }
}

__device__ __forceinline__ float gelu_exact(float x) {
    return 0.5f * x * (1.0f + erff(x * 0.70710678118654752f));
}

struct P2 { ull a, b; };   // 4 fp32 accumulators as 2 packed pairs

__global__ __launch_bounds__(BD, 1)
void tee_kernel(const int*   __restrict__ ids,
                const float* __restrict__ dates,
                const int*   __restrict__ lengths,
                const float* __restrict__ emb,
                const float* __restrict__ tp_w,  const float* __restrict__ tp_b,
                const float* __restrict__ tp_lnw, const float* __restrict__ tp_lnb,
                const float* __restrict__ w1, const float* __restrict__ b1,
                const float* __restrict__ ln1w, const float* __restrict__ ln1b,
                const float* __restrict__ w2, const float* __restrict__ b2,
                const float* __restrict__ ln2w, const float* __restrict__ ln2b,
                float* __restrict__ out, int B, int L)
{
    extern __shared__ float smem[];
    float* sw1   = smem;                      // 160*128  (80 KB)
    float* sw2   = sw1 + K1 * DD;             // 128*128  (64 KB)
    float* sxb   = sw2 + DD * DD;             // NW*TOK*160 (80 KB)
    float* spart = sxb;                       // aliased: used only after main loop

    const int b    = blockIdx.x;
    const int tid  = threadIdx.x;
    const int warp = tid >> 5;
    const int lane = tid & 31;
    const int f4   = lane * 4;

    for (int i = tid; i < K1 * DD; i += BD) sw1[i] = w1[i];
    for (int i = tid; i < DD * DD; i += BD) sw2[i] = w2[i];
    __syncthreads();

    const int len = lengths[b];

    const float4 bf1 = ld4(b1 + f4), l1w = ld4(ln1w + f4), l1b = ld4(ln1b + f4);
    const float4 bf2 = ld4(b2 + f4), l2w = ld4(ln2w + f4), l2b = ld4(ln2b + f4);
    const float tpw = tp_w[lane], tpb = tp_b[lane];
    const float tplw = tp_lnw[lane], tplb = tp_lnb[lane];

    float4 pool = make_float4(0.f, 0.f, 0.f, 0.f);
    float* xw = sxb + warp * (TOK * K1);

    const int ngroups = (len + TOK - 1) / TOK;   // masked tokens skipped
    for (int gi = warp; gi < ngroups; gi += NW) {
        const int l0 = gi * TOK;

        // ---- stage inputs: emb gather + temporal branch (Linear->LN->GELU) ----
        #pragma unroll
        for (int t = 0; t < TOK; t++) {
            int l = l0 + t; if (l >= L) l = L - 1;   // clamp; inactive tokens not pooled
            const int id = ids[b * L + l];
            const float* er = emb + id * DD;
            xw[t * K1 + lane]      = er[lane];
            xw[t * K1 + lane + 32] = er[lane + 32];
            xw[t * K1 + lane + 64] = er[lane + 64];
            xw[t * K1 + lane + 96] = er[lane + 96];

            const float dn = dates[b * L + l] * (1.0f / 1825.0f);
            const float v  = fmaf(dn, tpw, tpb);
            float s = v, sq = v * v;
            warp_sum2(s, sq);
            const float m   = s * (1.0f / TD);
            const float var = sq * (1.0f / TD) - m * m;
            const float rs  = rsqrtf(var + 1e-5f);
            const float u   = (v - m) * rs * tplw + tplb;
            xw[t * K1 + DD + lane] = gelu_exact(u);
        }
        __syncwarp();

        // ---- mm1: [TOK x 160] @ [160 x 128], packed f32x2 ----
        P2 acc[TOK];
        #pragma unroll
        for (int t = 0; t < TOK; t++) { acc[t].a = 0ull; acc[t].b = 0ull; }

        for (int k = 0; k < K1; k += 4) {
            const ulonglong2 w0 = *(const ulonglong2*)(sw1 + (k + 0) * DD + f4);
            const ulonglong2 w1r= *(const ulonglong2*)(sw1 + (k + 1) * DD + f4);
            const ulonglong2 w2r= *(const ulonglong2*)(sw1 + (k + 2) * DD + f4);
            const ulonglong2 w3r= *(const ulonglong2*)(sw1 + (k + 3) * DD + f4);
            #pragma unroll
            for (int t = 0; t < TOK; t++) {
                const float4 xv = ld4(xw + t * K1 + k);
                const ull x0 = splat2(xv.x), x1 = splat2(xv.y);
                const ull x2 = splat2(xv.z), x3 = splat2(xv.w);
                FMA2(acc[t].a, w0.x, x0);  FMA2(acc[t].b, w0.y, x0);
                FMA2(acc[t].a, w1r.x, x1); FMA2(acc[t].b, w1r.y, x1);
                FMA2(acc[t].a, w2r.x, x2); FMA2(acc[t].b, w2r.y, x2);
                FMA2(acc[t].a, w3r.x, x3); FMA2(acc[t].b, w3r.y, x3);
            }
        }

        // ---- LN1 + GELU, write activations back for mm2 ----
        #pragma unroll
        for (int t = 0; t < TOK; t++) {
            float4 y;
            unpack2(acc[t].a, y.x, y.y);
            unpack2(acc[t].b, y.z, y.w);
            y.x += bf1.x; y.y += bf1.y; y.z += bf1.z; y.w += bf1.w;
            float s  = y.x + y.y + y.z + y.w;
            float sq = y.x * y.x + y.y * y.y + y.z * y.z + y.w * y.w;
            warp_sum2(s, sq);
            const float m   = s * (1.0f / DD);
            const float var = sq * (1.0f / DD) - m * m;
            const float rs  = rsqrtf(var + 1e-5f);
            float4 g;
            g.x = gelu_exact((y.x - m) * rs * l1w.x + l1b.x);
            g.y = gelu_exact((y.y - m) * rs * l1w.y + l1b.y);
            g.z = gelu_exact((y.z - m) * rs * l1w.z + l1b.z);
            g.w = gelu_exact((y.w - m) * rs * l1w.w + l1b.w);
            *(float4*)(xw + t * K1 + f4) = g;
        }
        __syncwarp();

        // ---- mm2: [TOK x 128] @ [128 x 128], packed f32x2 ----
        #pragma unroll
        for (int t = 0; t < TOK; t++) { acc[t].a = 0ull; acc[t].b = 0ull; }

        for (int k = 0; k < DD; k += 4) {
            const ulonglong2 w0 = *(const ulonglong2*)(sw2 + (k + 0) * DD + f4);
            const ulonglong2 w1r= *(const ulonglong2*)(sw2 + (k + 1) * DD + f4);
            const ulonglong2 w2r= *(const ulonglong2*)(sw2 + (k + 2) * DD + f4);
            const ulonglong2 w3r= *(const ulonglong2*)(sw2 + (k + 3) * DD + f4);
            #pragma unroll
            for (int t = 0; t < TOK; t++) {
                const float4 xv = ld4(xw + t * K1 + k);
                const ull x0 = splat2(xv.x), x1 = splat2(xv.y);
                const ull x2 = splat2(xv.z), x3 = splat2(xv.w);
                FMA2(acc[t].a, w0.x, x0);  FMA2(acc[t].b, w0.y, x0);
                FMA2(acc[t].a, w1r.x, x1); FMA2(acc[t].b, w1r.y, x1);
                FMA2(acc[t].a, w2r.x, x2); FMA2(acc[t].b, w2r.y, x2);
                FMA2(acc[t].a, w3r.x, x3); FMA2(acc[t].b, w3r.y, x3);
            }
        }

        // ---- LN2 + masked pooling ----
        #pragma unroll
        for (int t = 0; t < TOK; t++) {
            float4 y;
            unpack2(acc[t].a, y.x, y.y);
            unpack2(acc[t].b, y.z, y.w);
            y.x += bf2.x; y.y += bf2.y; y.z += bf2.z; y.w += bf2.w;
            float s  = y.x + y.y + y.z + y.w;
            float sq = y.x * y.x + y.y * y.y + y.z * y.z + y.w * y.w;
            warp_sum2(s, sq);
            const float m   = s * (1.0f / DD);
            const float var = sq * (1.0f / DD) - m * m;
            const float rs  = rsqrtf(var + 1e-5f);
            if (l0 + t < len) {
                pool.x += (y.x - m) * rs * l2w.x + l2b.x;
                pool.y += (y.y - m) * rs * l2w.y + l2b.y;
                pool.z += (y.z - m) * rs * l2w.z + l2b.z;
                pool.w += (y.w - m) * rs * l2w.w + l2b.w;
            }
        }
        __syncwarp();
    }

    // ---- cross-warp pooling reduction (spart aliases sxb; safe after barrier) ----
    __syncthreads();
    *(float4*)(spart + warp * DD + f4) = pool;
    __syncthreads();

    if (tid < DD) {
        float s = 0.f;
        #pragma unroll
        for (int w = 0; w < NW; w++) s += spart[w * DD + tid];
        out[b * DD + tid] = (len > 0) ? s / (float)len : 0.0f;
    }
}

extern "C" void kernel_launch(void* const* d_in, const int* in_sizes, int n_in,
                              void* d_out, int out_size)
{
    const int*   ids     = (const int*)  d_in[0];
    const float* dates   = (const float*)d_in[1];
    const int*   lengths = (const int*)  d_in[2];
    const float* emb     = (const float*)d_in[3];
    const float* tp_w    = (const float*)d_in[4];
    const float* tp_b    = (const float*)d_in[5];
    const float* tp_lnw  = (const float*)d_in[6];
    const float* tp_lnb  = (const float*)d_in[7];
    const float* w1      = (const float*)d_in[8];
    const float* b1      = (const float*)d_in[9];
    const float* ln1w    = (const float*)d_in[10];
    const float* ln1b    = (const float*)d_in[11];
    const float* w2      = (const float*)d_in[12];
    const float* b2      = (const float*)d_in[13];
    const float* ln2w    = (const float*)d_in[14];
    const float* ln2b    = (const float*)d_in[15];
    float* out = (float*)d_out;

    const int B = in_sizes[2];            // 4096
    const int L = in_sizes[0] / B;        // 200

    const size_t smem_bytes = (size_t)(K1 * DD + DD * DD + NW * TOK * K1) * sizeof(float);
    cudaFuncSetAttribute(tee_kernel, cudaFuncAttributeMaxDynamicSharedMemorySize, (int)smem_bytes);

    tee_kernel<<<B, BD, smem_bytes>>>(ids, dates, lengths, emb,
                                      tp_w, tp_b, tp_lnw, tp_lnb,
                                      w1, b1, ln1w, ln1b,
                                      w2, b2, ln2w, ln2b,
                                      out, B, L);
}

// round 10
// speedup vs baseline: 1.5436x; 1.1973x over previous
#include <cuda_runtime.h>
#include <math.h>

#define BD   512
#define NW   16
#define DD   128
#define K1   160
#define TD   32
#define TOK  16
#define AST  164          // activation row stride in floats (==4 mod 32: conflict-free frags)
#define NKT1 20           // mm1 k-tiles (160/8)
#define NKT2 16           // mm2 k-tiles (128/8)
#define NNT  16           // n-tiles (128/8)

// fragment-packed weights, tf32 bit patterns: [kt][nt][lane] -> (b0,b1)
__device__ uint2 g_wp[(NKT1 + NKT2) * NNT * 32];

__device__ __forceinline__ unsigned tf32_bits(float f) {
    unsigned u; asm("cvt.rna.tf32.f32 %0, %1;" : "=r"(u) : "f"(f)); return u;
}
__device__ __forceinline__ float4 ld4(const float* p) { return *(const float4*)p; }

__device__ __forceinline__ void mma8(float* d, unsigned a0, unsigned a1,
                                     unsigned a2, unsigned a3, uint2 b) {
    asm volatile(
        "mma.sync.aligned.m16n8k8.row.col.f32.tf32.tf32.f32 "
        "{%0,%1,%2,%3}, {%4,%5,%6,%7}, {%8,%9}, {%0,%1,%2,%3};"
        : "+f"(d[0]), "+f"(d[1]), "+f"(d[2]), "+f"(d[3])
        : "r"(a0), "r"(a1), "r"(a2), "r"(a3), "r"(b.x), "r"(b.y));
}

__device__ __forceinline__ float gelu_exact(float x) {
    return 0.5f * x * (1.0f + erff(x * 0.70710678118654752f));
}
__device__ __forceinline__ void warp_sum2(float& s, float& sq) {
    #pragma unroll
    for (int o = 16; o; o >>= 1) {
        s  += __shfl_xor_sync(0xffffffffu, s,  o);
        sq += __shfl_xor_sync(0xffffffffu, sq, o);
    }
}
// reduce over the 4-lane tig group (lanes xor 1, 2)
__device__ __forceinline__ float tig_sum(float v) {
    v += __shfl_xor_sync(0xffffffffu, v, 1);
    v += __shfl_xor_sync(0xffffffffu, v, 2);
    return v;
}

// ---------------- pack kernel: weights -> fragment order, tf32 ----------------
__global__ void pack_kernel(const float* __restrict__ w1, const float* __restrict__ w2) {
    int i = blockIdx.x * blockDim.x + threadIdx.x;
    const int T1 = NKT1 * NNT * 32;
    const int T2 = NKT2 * NNT * 32;
    if (i < T1) {
        int lane = i & 31, nt = (i >> 5) % NNT, kt = (i >> 5) / NNT;
        int g = lane >> 2, t = lane & 3;
        uint2 u;
        u.x = tf32_bits(w1[(kt * 8 + t)     * DD + nt * 8 + g]);
        u.y = tf32_bits(w1[(kt * 8 + t + 4) * DD + nt * 8 + g]);
        g_wp[i] = u;
    } else if (i < T1 + T2) {
        int j = i - T1;
        int lane = j & 31, nt = (j >> 5) % NNT, kt = (j >> 5) / NNT;
        int g = lane >> 2, t = lane & 3;
        uint2 u;
        u.x = tf32_bits(w2[(kt * 8 + t)     * DD + nt * 8 + g]);
        u.y = tf32_bits(w2[(kt * 8 + t + 4) * DD + nt * 8 + g]);
        g_wp[i] = u;
    }
}

// ---------------- main kernel: one CTA per batch row ----------------
__global__ __launch_bounds__(BD, 1)
void tee_mma(const int*   __restrict__ ids,
             const float* __restrict__ dates,
             const int*   __restrict__ lengths,
             const float* __restrict__ emb,
             const float* __restrict__ tp_w,  const float* __restrict__ tp_b,
             const float* __restrict__ tp_lnw, const float* __restrict__ tp_lnb,
             const float* __restrict__ b1,  const float* __restrict__ ln1w, const float* __restrict__ ln1b,
             const float* __restrict__ b2,  const float* __restrict__ ln2w, const float* __restrict__ ln2b,
             float* __restrict__ out, int B, int L)
{
    extern __shared__ float smem[];
    float* sxb   = smem;                        // NW * TOK * AST  (167936 B)
    float* spart = sxb + NW * TOK * AST;        // NW * DD         (8192 B)
    float* spar  = spart + NW * DD;             // 6 * DD          (3072 B)

    const int b    = blockIdx.x;
    const int tid  = threadIdx.x;
    const int warp = tid >> 5;
    const int lane = tid & 31;
    const int gid  = lane >> 2;    // row within m16 tile
    const int tig  = lane & 3;     // thread-in-group (k / col pair index)
    const int f4   = lane * 4;

    if (tid < DD) {
        spar[tid]          = b1[tid];
        spar[DD + tid]     = ln1w[tid];
        spar[2 * DD + tid] = ln1b[tid];
        spar[3 * DD + tid] = b2[tid];
    }
    __syncthreads();

    const int len = lengths[b];
    const float tpw = tp_w[lane], tpb = tp_b[lane];
    const float tplw = tp_lnw[lane], tplb = tp_lnb[lane];
    const float4 pl2w = ld4(ln2w + f4), pl2b = ld4(ln2b + f4);

    float4 pool = make_float4(0.f, 0.f, 0.f, 0.f);
    float* xw = sxb + warp * (TOK * AST);
    const uint2* wp1 = g_wp;
    const uint2* wp2 = g_wp + NKT1 * NNT * 32;

    const int ngroups = (len + TOK - 1) / TOK;
    for (int gi = warp; gi < ngroups; gi += NW) {
        const int l0 = gi * TOK;

        // ---- stage: embedding gather + temporal branch, tf32-rounded ----
        for (int t = 0; t < TOK; t++) {
            const int l = min(l0 + t, L - 1);
            const int id = ids[b * L + l];
            float4 e = ld4(emb + id * DD + f4);
            float4 ec;
            ec.x = __uint_as_float(tf32_bits(e.x));
            ec.y = __uint_as_float(tf32_bits(e.y));
            ec.z = __uint_as_float(tf32_bits(e.z));
            ec.w = __uint_as_float(tf32_bits(e.w));
            *(float4*)(xw + t * AST + f4) = ec;

            const float dn = dates[b * L + l] * (1.0f / 1825.0f);
            const float v  = fmaf(dn, tpw, tpb);
            float s = v, q = v * v;
            warp_sum2(s, q);
            const float m  = s * (1.0f / TD);
            const float rs = rsqrtf(q * (1.0f / TD) - m * m + 1e-5f);
            const float u  = (v - m) * rs * tplw + tplb;
            xw[t * AST + DD + lane] = __uint_as_float(tf32_bits(gelu_exact(u)));
        }
        __syncwarp();

        // ---- mm1: [16 x 160] @ [160 x 128] on tensor cores ----
        float D1[NNT][4];
        #pragma unroll
        for (int nt = 0; nt < NNT; nt++) { D1[nt][0]=0.f; D1[nt][1]=0.f; D1[nt][2]=0.f; D1[nt][3]=0.f; }

        const float* r0 = xw + gid * AST;
        const float* r1 = xw + (gid + 8) * AST;
        for (int kt = 0; kt < NKT1; kt++) {
            const int k0 = kt * 8;
            const unsigned a0 = __float_as_uint(r0[k0 + tig]);
            const unsigned a1 = __float_as_uint(r1[k0 + tig]);
            const unsigned a2 = __float_as_uint(r0[k0 + tig + 4]);
            const unsigned a3 = __float_as_uint(r1[k0 + tig + 4]);
            #pragma unroll
            for (int h = 0; h < 2; h++) {
                uint2 bb[8];
                #pragma unroll
                for (int j = 0; j < 8; j++) bb[j] = wp1[(kt * NNT + h * 8 + j) * 32 + lane];
                #pragma unroll
                for (int j = 0; j < 8; j++) mma8(D1[h * 8 + j], a0, a1, a2, a3, bb[j]);
            }
        }

        // ---- ep1: +bias, LN1 (stats on fragments), GELU, store tf32 back ----
        float s0 = 0.f, q0 = 0.f, s1 = 0.f, q1 = 0.f;
        #pragma unroll
        for (int nt = 0; nt < NNT; nt++) {
            const int c = nt * 8 + 2 * tig;
            const float2 bb = *(const float2*)(spar + c);
            D1[nt][0] += bb.x; D1[nt][1] += bb.y; D1[nt][2] += bb.x; D1[nt][3] += bb.y;
            s0 += D1[nt][0] + D1[nt][1]; q0 += D1[nt][0]*D1[nt][0] + D1[nt][1]*D1[nt][1];
            s1 += D1[nt][2] + D1[nt][3]; q1 += D1[nt][2]*D1[nt][2] + D1[nt][3]*D1[nt][3];
        }
        s0 = tig_sum(s0); q0 = tig_sum(q0); s1 = tig_sum(s1); q1 = tig_sum(q1);
        const float m0 = s0 * (1.0f / DD), rs0 = rsqrtf(q0 * (1.0f / DD) - m0 * m0 + 1e-5f);
        const float m1 = s1 * (1.0f / DD), rs1 = rsqrtf(q1 * (1.0f / DD) - m1 * m1 + 1e-5f);
        #pragma unroll
        for (int nt = 0; nt < NNT; nt++) {
            const int c = nt * 8 + 2 * tig;
            const float2 lw = *(const float2*)(spar + DD + c);
            const float2 lb = *(const float2*)(spar + 2 * DD + c);
            float g0 = gelu_exact((D1[nt][0] - m0) * rs0 * lw.x + lb.x);
            float g1 = gelu_exact((D1[nt][1] - m0) * rs0 * lw.y + lb.y);
            float g2 = gelu_exact((D1[nt][2] - m1) * rs1 * lw.x + lb.x);
            float g3 = gelu_exact((D1[nt][3] - m1) * rs1 * lw.y + lb.y);
            float2 v0, v1;
            v0.x = __uint_as_float(tf32_bits(g0)); v0.y = __uint_as_float(tf32_bits(g1));
            v1.x = __uint_as_float(tf32_bits(g2)); v1.y = __uint_as_float(tf32_bits(g3));
            *(float2*)(xw + gid * AST + c)       = v0;
            *(float2*)(xw + (gid + 8) * AST + c) = v1;
        }
        __syncwarp();

        // ---- mm2: A frags into registers, then 16 n-tiles ----
        unsigned A2[NKT2][4];
        #pragma unroll
        for (int kt = 0; kt < NKT2; kt++) {
            const int k0 = kt * 8;
            A2[kt][0] = __float_as_uint(xw[gid * AST + k0 + tig]);
            A2[kt][1] = __float_as_uint(xw[(gid + 8) * AST + k0 + tig]);
            A2[kt][2] = __float_as_uint(xw[gid * AST + k0 + tig + 4]);
            A2[kt][3] = __float_as_uint(xw[(gid + 8) * AST + k0 + tig + 4]);
        }
        __syncwarp();

        float s20 = 0.f, q20 = 0.f, s21 = 0.f, q21 = 0.f;
        for (int nt = 0; nt < NNT; nt++) {
            float D2[4] = {0.f, 0.f, 0.f, 0.f};
            #pragma unroll
            for (int h = 0; h < 2; h++) {
                uint2 bb[8];
                #pragma unroll
                for (int j = 0; j < 8; j++) bb[j] = wp2[((h * 8 + j) * NNT + nt) * 32 + lane];
                #pragma unroll
                for (int j = 0; j < 8; j++) mma8(D2, A2[h*8+j][0], A2[h*8+j][1], A2[h*8+j][2], A2[h*8+j][3], bb[j]);
            }
            const int c = nt * 8 + 2 * tig;
            const float2 b2v = *(const float2*)(spar + 3 * DD + c);
            D2[0] += b2v.x; D2[1] += b2v.y; D2[2] += b2v.x; D2[3] += b2v.y;
            s20 += D2[0] + D2[1]; q20 += D2[0]*D2[0] + D2[1]*D2[1];
            s21 += D2[2] + D2[3]; q21 += D2[2]*D2[2] + D2[3]*D2[3];
            *(float2*)(xw + gid * AST + c)       = make_float2(D2[0], D2[1]);
            *(float2*)(xw + (gid + 8) * AST + c) = make_float2(D2[2], D2[3]);
        }
        s20 = tig_sum(s20); q20 = tig_sum(q20); s21 = tig_sum(s21); q21 = tig_sum(q21);
        const float mm0 = s20 * (1.0f / DD), rr0 = rsqrtf(q20 * (1.0f / DD) - mm0 * mm0 + 1e-5f);
        const float mm1v = s21 * (1.0f / DD), rr1 = rsqrtf(q21 * (1.0f / DD) - mm1v * mm1v + 1e-5f);
        if (tig == 0) {
            xw[gid * AST + 160] = mm0;  xw[gid * AST + 161] = rr0;
            xw[(gid + 8) * AST + 160] = mm1v; xw[(gid + 8) * AST + 161] = rr1;
        }
        __syncwarp();

        // ---- LN2 + masked pooling (lane owns feature quad f4) ----
        #pragma unroll
        for (int t = 0; t < TOK; t++) {
            if (l0 + t < len) {
                const float4 v = ld4(xw + t * AST + f4);
                const float m  = xw[t * AST + 160];
                const float rs = xw[t * AST + 161];
                pool.x += (v.x - m) * rs * pl2w.x + pl2b.x;
                pool.y += (v.y - m) * rs * pl2w.y + pl2b.y;
                pool.z += (v.z - m) * rs * pl2w.z + pl2b.z;
                pool.w += (v.w - m) * rs * pl2w.w + pl2b.w;
            }
        }
        __syncwarp();
    }

    // ---- cross-warp pooling reduction ----
    __syncthreads();
    *(float4*)(spart + warp * DD + f4) = pool;
    __syncthreads();
    if (tid < DD) {
        float s = 0.f;
        #pragma unroll
        for (int w = 0; w < NW; w++) s += spart[w * DD + tid];
        out[b * DD + tid] = (len > 0) ? s / (float)len : 0.0f;
    }
}

extern "C" void kernel_launch(void* const* d_in, const int* in_sizes, int n_in,
                              void* d_out, int out_size)
{
    const int*   ids     = (const int*)  d_in[0];
    const float* dates   = (const float*)d_in[1];
    const int*   lengths = (const int*)  d_in[2];
    const float* emb     = (const float*)d_in[3];
    const float* tp_w    = (const float*)d_in[4];
    const float* tp_b    = (const float*)d_in[5];
    const float* tp_lnw  = (const float*)d_in[6];
    const float* tp_lnb  = (const float*)d_in[7];
    const float* w1      = (const float*)d_in[8];
    const float* b1      = (const float*)d_in[9];
    const float* ln1w    = (const float*)d_in[10];
    const float* ln1b    = (const float*)d_in[11];
    const float* w2      = (const float*)d_in[12];
    const float* b2      = (const float*)d_in[13];
    const float* ln2w    = (const float*)d_in[14];
    const float* ln2b    = (const float*)d_in[15];
    float* out = (float*)d_out;

    const int B = in_sizes[2];            // 4096
    const int L = in_sizes[0] / B;        // 200

    const int npack = (NKT1 + NKT2) * NNT * 32;
    pack_kernel<<<(npack + 255) / 256, 256>>>(w1, w2);

    const size_t smem_bytes = (size_t)(NW * TOK * AST + NW * DD + 6 * DD) * sizeof(float);
    cudaFuncSetAttribute(tee_mma, cudaFuncAttributeMaxDynamicSharedMemorySize, (int)smem_bytes);
    tee_mma<<<B, BD, smem_bytes>>>(ids, dates, lengths, emb,
                                   tp_w, tp_b, tp_lnw, tp_lnb,
                                   b1, ln1w, ln1b, b2, ln2w, ln2b,
                                   out, B, L);
}

// round 11
// speedup vs baseline: 1.8113x; 1.1734x over previous
#include <cuda_runtime.h>
#include <math.h>

#define BD   256
#define NW   8
#define DD   128
#define K1   160
#define TD   32
#define TOK  16
#define NKT1 20           // mm1 k-tiles (160/8)
#define NKT2 16           // mm2 k-tiles (128/8)
#define NNT  16           // n-tiles (128/8)
#define WPN  ((NKT1 + NKT2) * NNT * 32)   // total packed uint2 frags

// fragment-packed weights, tf32 bit patterns: [kt][nt][lane] -> (b0,b1)
__device__ uint2 g_wp[WPN];

__device__ __forceinline__ unsigned tf32_bits(float f) {
    unsigned u; asm("cvt.rna.tf32.f32 %0, %1;" : "=r"(u) : "f"(f)); return u;
}
__device__ __forceinline__ float4 ld4(const float* p) { return *(const float4*)p; }

__device__ __forceinline__ void mma8(float* d, unsigned a0, unsigned a1,
                                     unsigned a2, unsigned a3, uint2 b) {
    asm volatile(
        "mma.sync.aligned.m16n8k8.row.col.f32.tf32.tf32.f32 "
        "{%0,%1,%2,%3}, {%4,%5,%6,%7}, {%8,%9}, {%0,%1,%2,%3};"
        : "+f"(d[0]), "+f"(d[1]), "+f"(d[2]), "+f"(d[3])
        : "r"(a0), "r"(a1), "r"(a2), "r"(a3), "r"(b.x), "r"(b.y));
}

__device__ __forceinline__ float gelu_exact(float x) {
    return 0.5f * x * (1.0f + erff(x * 0.70710678118654752f));
}
__device__ __forceinline__ void warp_sum2(float& s, float& sq) {
    #pragma unroll
    for (int o = 16; o; o >>= 1) {
        s  += __shfl_xor_sync(0xffffffffu, s,  o);
        sq += __shfl_xor_sync(0xffffffffu, sq, o);
    }
}
__device__ __forceinline__ float tig_sum(float v) {
    v += __shfl_xor_sync(0xffffffffu, v, 1);
    v += __shfl_xor_sync(0xffffffffu, v, 2);
    return v;
}

// swizzled activation index: token t, feature k. stride 160; XOR keeps
// A-fragment LDS (fixed k, varying t=gid) on distinct banks.
__device__ __forceinline__ int swx(int t, int k) {
    return t * 160 + (k ^ ((t & 7) << 2));
}

// ---------------- pack kernel: weights -> fragment order, tf32 ----------------
__global__ void pack_kernel(const float* __restrict__ w1, const float* __restrict__ w2) {
    int i = blockIdx.x * blockDim.x + threadIdx.x;
    const int T1 = NKT1 * NNT * 32;
    const int T2 = NKT2 * NNT * 32;
    if (i < T1) {
        int lane = i & 31, nt = (i >> 5) % NNT, kt = (i >> 5) / NNT;
        int g = lane >> 2, t = lane & 3;
        uint2 u;
        u.x = tf32_bits(w1[(kt * 8 + t)     * DD + nt * 8 + g]);
        u.y = tf32_bits(w1[(kt * 8 + t + 4) * DD + nt * 8 + g]);
        g_wp[i] = u;
    } else if (i < T1 + T2) {
        int j = i - T1;
        int lane = j & 31, nt = (j >> 5) % NNT, kt = (j >> 5) / NNT;
        int g = lane >> 2, t = lane & 3;
        uint2 u;
        u.x = tf32_bits(w2[(kt * 8 + t)     * DD + nt * 8 + g]);
        u.y = tf32_bits(w2[(kt * 8 + t + 4) * DD + nt * 8 + g]);
        g_wp[i] = u;
    }
}

// ---------------- main kernel: one CTA per batch row ----------------
__global__ __launch_bounds__(BD, 1)
void tee_mma(const int*   __restrict__ ids,
             const float* __restrict__ dates,
             const int*   __restrict__ lengths,
             const float* __restrict__ emb,
             const float* __restrict__ tp_w,  const float* __restrict__ tp_b,
             const float* __restrict__ tp_lnw, const float* __restrict__ tp_lnb,
             const float* __restrict__ b1,  const float* __restrict__ ln1w, const float* __restrict__ ln1b,
             const float* __restrict__ b2,  const float* __restrict__ ln2w, const float* __restrict__ ln2b,
             float* __restrict__ out, int B, int L)
{
    extern __shared__ float smem[];
    uint2* s_wp  = (uint2*)smem;                 // 147456 B packed weight frags
    float* sxb   = smem + WPN * 2;               // NW*TOK*160 floats (81920 B)
    float* spar  = sxb + NW * TOK * 160;         // 4*DD params (2048 B)
    float* spart = sxb;                          // pooling partials (alias, post-loop)

    const int b    = blockIdx.x;
    const int tid  = threadIdx.x;
    const int warp = tid >> 5;
    const int lane = tid & 31;
    const int gid  = lane >> 2;    // row within m16 tile
    const int tig  = lane & 3;     // thread-in-group
    const int f4   = lane * 4;

    // stage packed weights + params into SMEM
    {
        const uint4* src = (const uint4*)g_wp;
        uint4* dst = (uint4*)s_wp;
        for (int i = tid; i < WPN / 2; i += BD) dst[i] = src[i];
    }
    if (tid < DD) {
        spar[tid]          = b1[tid];
        spar[DD + tid]     = ln1w[tid];
        spar[2 * DD + tid] = ln1b[tid];
        spar[3 * DD + tid] = b2[tid];
    }
    __syncthreads();

    const int len = lengths[b];
    const float tpw = tp_w[lane], tpb = tp_b[lane];
    const float tplw = tp_lnw[lane], tplb = tp_lnb[lane];
    const float4 pl2w = ld4(ln2w + f4), pl2b = ld4(ln2b + f4);

    float4 pool = make_float4(0.f, 0.f, 0.f, 0.f);
    float* xw = sxb + warp * (TOK * 160);
    const uint2* wp1 = s_wp;
    const uint2* wp2 = s_wp + NKT1 * NNT * 32;

    const int ngroups = (len + TOK - 1) / TOK;
    for (int gi = warp; gi < ngroups; gi += NW) {
        const int l0 = gi * TOK;

        // ---- stage: embedding gather + temporal branch, tf32-rounded ----
        for (int t = 0; t < TOK; t++) {
            const int l = min(l0 + t, L - 1);
            const int id = ids[b * L + l];
            float4 e = ld4(emb + id * DD + f4);
            float4 ec;
            ec.x = __uint_as_float(tf32_bits(e.x));
            ec.y = __uint_as_float(tf32_bits(e.y));
            ec.z = __uint_as_float(tf32_bits(e.z));
            ec.w = __uint_as_float(tf32_bits(e.w));
            *(float4*)(xw + swx(t, f4)) = ec;

            const float dn = dates[b * L + l] * (1.0f / 1825.0f);
            const float v  = fmaf(dn, tpw, tpb);
            float s = v, q = v * v;
            warp_sum2(s, q);
            const float m  = s * (1.0f / TD);
            const float rs = rsqrtf(q * (1.0f / TD) - m * m + 1e-5f);
            const float u  = (v - m) * rs * tplw + tplb;
            xw[swx(t, DD + lane)] = __uint_as_float(tf32_bits(gelu_exact(u)));
        }
        __syncwarp();

        // ---- mm1: [16 x 160] @ [160 x 128] on tensor cores ----
        float D1[NNT][4];
        #pragma unroll
        for (int nt = 0; nt < NNT; nt++) { D1[nt][0]=0.f; D1[nt][1]=0.f; D1[nt][2]=0.f; D1[nt][3]=0.f; }

        for (int kt = 0; kt < NKT1; kt++) {
            const int k0 = kt * 8;
            const unsigned a0 = __float_as_uint(xw[swx(gid,     k0 + tig)]);
            const unsigned a1 = __float_as_uint(xw[swx(gid + 8, k0 + tig)]);
            const unsigned a2 = __float_as_uint(xw[swx(gid,     k0 + tig + 4)]);
            const unsigned a3 = __float_as_uint(xw[swx(gid + 8, k0 + tig + 4)]);
            #pragma unroll
            for (int h = 0; h < 2; h++) {
                uint2 bb[8];
                #pragma unroll
                for (int j = 0; j < 8; j++) bb[j] = wp1[(kt * NNT + h * 8 + j) * 32 + lane];
                #pragma unroll
                for (int j = 0; j < 8; j++) mma8(D1[h * 8 + j], a0, a1, a2, a3, bb[j]);
            }
        }

        // ---- ep1: +bias, LN1 (stats on fragments), GELU, store tf32 back ----
        float s0 = 0.f, q0 = 0.f, s1 = 0.f, q1 = 0.f;
        #pragma unroll
        for (int nt = 0; nt < NNT; nt++) {
            const int c = nt * 8 + 2 * tig;
            const float2 bb = *(const float2*)(spar + c);
            D1[nt][0] += bb.x; D1[nt][1] += bb.y; D1[nt][2] += bb.x; D1[nt][3] += bb.y;
            s0 += D1[nt][0] + D1[nt][1]; q0 += D1[nt][0]*D1[nt][0] + D1[nt][1]*D1[nt][1];
            s1 += D1[nt][2] + D1[nt][3]; q1 += D1[nt][2]*D1[nt][2] + D1[nt][3]*D1[nt][3];
        }
        s0 = tig_sum(s0); q0 = tig_sum(q0); s1 = tig_sum(s1); q1 = tig_sum(q1);
        const float m0 = s0 * (1.0f / DD), rs0 = rsqrtf(q0 * (1.0f / DD) - m0 * m0 + 1e-5f);
        const float m1 = s1 * (1.0f / DD), rs1 = rsqrtf(q1 * (1.0f / DD) - m1 * m1 + 1e-5f);
        #pragma unroll
        for (int nt = 0; nt < NNT; nt++) {
            const int c = nt * 8 + 2 * tig;
            const float2 lw = *(const float2*)(spar + DD + c);
            const float2 lb = *(const float2*)(spar + 2 * DD + c);
            float g0 = gelu_exact((D1[nt][0] - m0) * rs0 * lw.x + lb.x);
            float g1 = gelu_exact((D1[nt][1] - m0) * rs0 * lw.y + lb.y);
            float g2 = gelu_exact((D1[nt][2] - m1) * rs1 * lw.x + lb.x);
            float g3 = gelu_exact((D1[nt][3] - m1) * rs1 * lw.y + lb.y);
            float2 v0, v1;
            v0.x = __uint_as_float(tf32_bits(g0)); v0.y = __uint_as_float(tf32_bits(g1));
            v1.x = __uint_as_float(tf32_bits(g2)); v1.y = __uint_as_float(tf32_bits(g3));
            *(float2*)(xw + swx(gid,     c)) = v0;
            *(float2*)(xw + swx(gid + 8, c)) = v1;
        }
        __syncwarp();

        // ---- mm2: A frags into registers, then 16 n-tiles ----
        unsigned A2[NKT2][4];
        #pragma unroll
        for (int kt = 0; kt < NKT2; kt++) {
            const int k0 = kt * 8;
            A2[kt][0] = __float_as_uint(xw[swx(gid,     k0 + tig)]);
            A2[kt][1] = __float_as_uint(xw[swx(gid + 8, k0 + tig)]);
            A2[kt][2] = __float_as_uint(xw[swx(gid,     k0 + tig + 4)]);
            A2[kt][3] = __float_as_uint(xw[swx(gid + 8, k0 + tig + 4)]);
        }
        __syncwarp();

        float s20 = 0.f, q20 = 0.f, s21 = 0.f, q21 = 0.f;
        for (int nt = 0; nt < NNT; nt++) {
            float D2[4] = {0.f, 0.f, 0.f, 0.f};
            #pragma unroll
            for (int h = 0; h < 2; h++) {
                uint2 bb[8];
                #pragma unroll
                for (int j = 0; j < 8; j++) bb[j] = wp2[((h * 8 + j) * NNT + nt) * 32 + lane];
                #pragma unroll
                for (int j = 0; j < 8; j++) mma8(D2, A2[h*8+j][0], A2[h*8+j][1], A2[h*8+j][2], A2[h*8+j][3], bb[j]);
            }
            const int c = nt * 8 + 2 * tig;
            const float2 b2v = *(const float2*)(spar + 3 * DD + c);
            D2[0] += b2v.x; D2[1] += b2v.y; D2[2] += b2v.x; D2[3] += b2v.y;
            s20 += D2[0] + D2[1]; q20 += D2[0]*D2[0] + D2[1]*D2[1];
            s21 += D2[2] + D2[3]; q21 += D2[2]*D2[2] + D2[3]*D2[3];
            *(float2*)(xw + swx(gid,     c)) = make_float2(D2[0], D2[1]);
            *(float2*)(xw + swx(gid + 8, c)) = make_float2(D2[2], D2[3]);
        }
        s20 = tig_sum(s20); q20 = tig_sum(q20); s21 = tig_sum(s21); q21 = tig_sum(q21);
        const float mm0 = s20 * (1.0f / DD), rr0 = rsqrtf(q20 * (1.0f / DD) - mm0 * mm0 + 1e-5f);
        const float mm1v = s21 * (1.0f / DD), rr1 = rsqrtf(q21 * (1.0f / DD) - mm1v * mm1v + 1e-5f);
        __syncwarp();

        // ---- LN2 + masked pooling; stats broadcast via shfl (no smem) ----
        #pragma unroll
        for (int t = 0; t < TOK; t++) {
            const float mt  = __shfl_sync(0xffffffffu, (t < 8) ? mm0 : mm1v, (t & 7) << 2);
            const float rst = __shfl_sync(0xffffffffu, (t < 8) ? rr0 : rr1,  (t & 7) << 2);
            if (l0 + t < len) {
                const float4 v = ld4(xw + swx(t, f4));
                pool.x += (v.x - mt) * rst * pl2w.x + pl2b.x;
                pool.y += (v.y - mt) * rst * pl2w.y + pl2b.y;
                pool.z += (v.z - mt) * rst * pl2w.z + pl2b.z;
                pool.w += (v.w - mt) * rst * pl2w.w + pl2b.w;
            }
        }
        __syncwarp();
    }

    // ---- cross-warp pooling reduction (spart aliases sxb; safe after barrier) ----
    __syncthreads();
    *(float4*)(spart + warp * DD + f4) = pool;
    __syncthreads();
    if (tid < DD) {
        float s = 0.f;
        #pragma unroll
        for (int w = 0; w < NW; w++) s += spart[w * DD + tid];
        out[b * DD + tid] = (len > 0) ? s / (float)len : 0.0f;
    }
}

extern "C" void kernel_launch(void* const* d_in, const int* in_sizes, int n_in,
                              void* d_out, int out_size)
{
    const int*   ids     = (const int*)  d_in[0];
    const float* dates   = (const float*)d_in[1];
    const int*   lengths = (const int*)  d_in[2];
    const float* emb     = (const float*)d_in[3];
    const float* tp_w    = (const float*)d_in[4];
    const float* tp_b    = (const float*)d_in[5];
    const float* tp_lnw  = (const float*)d_in[6];
    const float* tp_lnb  = (const float*)d_in[7];
    const float* w1      = (const float*)d_in[8];
    const float* b1      = (const float*)d_in[9];
    const float* ln1w    = (const float*)d_in[10];
    const float* ln1b    = (const float*)d_in[11];
    const float* w2      = (const float*)d_in[12];
    const float* b2      = (const float*)d_in[13];
    const float* ln2w    = (const float*)d_in[14];
    const float* ln2b    = (const float*)d_in[15];
    float* out = (float*)d_out;

    const int B = in_sizes[2];            // 4096
    const int L = in_sizes[0] / B;        // 200

    pack_kernel<<<(WPN + 255) / 256, 256>>>(w1, w2);

    const size_t smem_bytes = (size_t)WPN * 8 + (size_t)(NW * TOK * 160 + 4 * DD) * sizeof(float);
    cudaFuncSetAttribute(tee_mma, cudaFuncAttributeMaxDynamicSharedMemorySize, (int)smem_bytes);
    tee_mma<<<B, BD, smem_bytes>>>(ids, dates, lengths, emb,
                                   tp_w, tp_b, tp_lnw, tp_lnb,
                                   b1, ln1w, ln1b, b2, ln2w, ln2b,
                                   out, B, L);
}

// round 12
// speedup vs baseline: 2.0122x; 1.1109x over previous
#include <cuda_runtime.h>
#include <math.h>

#define BD   256
#define NW   8            // warps per CTA == rows per CTA
#define DD   128
#define K1   160
#define TD   32
#define TOK  16
#define NKT1 20           // mm1 k-tiles (160/8)
#define NKT2 16           // mm2 k-tiles (128/8)
#define NNT  16           // n-tiles (128/8)
#define WPN  ((NKT1 + NKT2) * NNT * 32)   // total packed uint2 frags

// fragment-packed weights, tf32 bit patterns: [kt][nt][lane] -> (b0,b1)
__device__ uint2 g_wp[WPN];

__device__ __forceinline__ unsigned tf32_bits(float f) {
    unsigned u; asm("cvt.rna.tf32.f32 %0, %1;" : "=r"(u) : "f"(f)); return u;
}
__device__ __forceinline__ float4 ld4(const float* p) { return *(const float4*)p; }

__device__ __forceinline__ void mma8(float* d, unsigned a0, unsigned a1,
                                     unsigned a2, unsigned a3, uint2 b) {
    asm volatile(
        "mma.sync.aligned.m16n8k8.row.col.f32.tf32.tf32.f32 "
        "{%0,%1,%2,%3}, {%4,%5,%6,%7}, {%8,%9}, {%0,%1,%2,%3};"
        : "+f"(d[0]), "+f"(d[1]), "+f"(d[2]), "+f"(d[3])
        : "r"(a0), "r"(a1), "r"(a2), "r"(a3), "r"(b.x), "r"(b.y));
}

__device__ __forceinline__ float gelu_exact(float x) {
    return 0.5f * x * (1.0f + erff(x * 0.70710678118654752f));
}
__device__ __forceinline__ void warp_sum2(float& s, float& sq) {
    #pragma unroll
    for (int o = 16; o; o >>= 1) {
        s  += __shfl_xor_sync(0xffffffffu, s,  o);
        sq += __shfl_xor_sync(0xffffffffu, sq, o);
    }
}
__device__ __forceinline__ float tig_sum(float v) {
    v += __shfl_xor_sync(0xffffffffu, v, 1);
    v += __shfl_xor_sync(0xffffffffu, v, 2);
    return v;
}

// swizzled activation index: token t, feature k. stride 160; XOR keeps
// A-fragment LDS (fixed k, varying t=gid) on distinct banks.
__device__ __forceinline__ int swx(int t, int k) {
    return t * 160 + (k ^ ((t & 7) << 2));
}

// ---------------- pack kernel: weights -> fragment order, tf32 ----------------
__global__ void pack_kernel(const float* __restrict__ w1, const float* __restrict__ w2) {
    int i = blockIdx.x * blockDim.x + threadIdx.x;
    const int T1 = NKT1 * NNT * 32;
    const int T2 = NKT2 * NNT * 32;
    if (i < T1) {
        int lane = i & 31, nt = (i >> 5) % NNT, kt = (i >> 5) / NNT;
        int g = lane >> 2, t = lane & 3;
        uint2 u;
        u.x = tf32_bits(w1[(kt * 8 + t)     * DD + nt * 8 + g]);
        u.y = tf32_bits(w1[(kt * 8 + t + 4) * DD + nt * 8 + g]);
        g_wp[i] = u;
    } else if (i < T1 + T2) {
        int j = i - T1;
        int lane = j & 31, nt = (j >> 5) % NNT, kt = (j >> 5) / NNT;
        int g = lane >> 2, t = lane & 3;
        uint2 u;
        u.x = tf32_bits(w2[(kt * 8 + t)     * DD + nt * 8 + g]);
        u.y = tf32_bits(w2[(kt * 8 + t + 4) * DD + nt * 8 + g]);
        g_wp[i] = u;
    }
}

// ---------------- main kernel: one WARP per batch row ----------------
__global__ __launch_bounds__(BD, 1)
void tee_mma(const int*   __restrict__ ids,
             const float* __restrict__ dates,
             const int*   __restrict__ lengths,
             const float* __restrict__ emb,
             const float* __restrict__ tp_w,  const float* __restrict__ tp_b,
             const float* __restrict__ tp_lnw, const float* __restrict__ tp_lnb,
             const float* __restrict__ b1,  const float* __restrict__ ln1w, const float* __restrict__ ln1b,
             const float* __restrict__ b2,  const float* __restrict__ ln2w, const float* __restrict__ ln2b,
             float* __restrict__ out, int B, int L)
{
    extern __shared__ float smem[];
    uint2* s_wp  = (uint2*)smem;                 // 147456 B packed weight frags
    float* sxb   = smem + WPN * 2;               // NW*TOK*160 floats (81920 B)
    float* spar  = sxb + NW * TOK * 160;         // 4*DD params (2048 B)

    const int tid  = threadIdx.x;
    const int warp = tid >> 5;
    const int lane = tid & 31;
    const int gid  = lane >> 2;    // row within m16 tile
    const int tig  = lane & 3;     // thread-in-group
    const int f4   = lane * 4;
    const int row  = blockIdx.x * NW + warp;   // batch row owned by this warp

    // stage packed weights + params into SMEM (once per 8 rows)
    {
        const uint4* src = (const uint4*)g_wp;
        uint4* dst = (uint4*)s_wp;
        for (int i = tid; i < WPN / 2; i += BD) dst[i] = src[i];
    }
    if (tid < DD) {
        spar[tid]          = b1[tid];
        spar[DD + tid]     = ln1w[tid];
        spar[2 * DD + tid] = ln1b[tid];
        spar[3 * DD + tid] = b2[tid];
    }
    __syncthreads();

    if (row >= B) return;
    const int len = lengths[row];

    const float tpw = tp_w[lane], tpb = tp_b[lane];
    const float tplw = tp_lnw[lane], tplb = tp_lnb[lane];
    const float4 pl2w = ld4(ln2w + f4), pl2b = ld4(ln2b + f4);

    float4 pool = make_float4(0.f, 0.f, 0.f, 0.f);
    float* xw = sxb + warp * (TOK * 160);
    const uint2* wp1 = s_wp;
    const uint2* wp2 = s_wp + NKT1 * NNT * 32;

    const int ngroups = (len + TOK - 1) / TOK;
    for (int gi = 0; gi < ngroups; gi++) {
        const int l0 = gi * TOK;

        // ---- coalesced group prefetch: lanes 0..15 fetch ids/dates ----
        int   idv = 0;
        float dtv = 0.f;
        if (lane < TOK) {
            const int l = min(l0 + lane, L - 1);
            idv = ids[row * L + l];
            dtv = dates[row * L + l];
        }

        // ---- stage: embedding gather (batched, MLP=16), tf32-rounded ----
        #pragma unroll
        for (int t = 0; t < TOK; t++) {
            const int id = __shfl_sync(0xffffffffu, idv, t);
            float4 e = ld4(emb + id * DD + f4);
            float4 ec;
            ec.x = __uint_as_float(tf32_bits(e.x));
            ec.y = __uint_as_float(tf32_bits(e.y));
            ec.z = __uint_as_float(tf32_bits(e.z));
            ec.w = __uint_as_float(tf32_bits(e.w));
            *(float4*)(xw + swx(t, f4)) = ec;
        }
        // ---- temporal branch: Linear(1->32) + LN + GELU per token ----
        #pragma unroll
        for (int t = 0; t < TOK; t++) {
            const float dn = __shfl_sync(0xffffffffu, dtv, t) * (1.0f / 1825.0f);
            const float v  = fmaf(dn, tpw, tpb);
            float s = v, q = v * v;
            warp_sum2(s, q);
            const float m  = s * (1.0f / TD);
            const float rs = rsqrtf(q * (1.0f / TD) - m * m + 1e-5f);
            const float u  = (v - m) * rs * tplw + tplb;
            xw[swx(t, DD + lane)] = __uint_as_float(tf32_bits(gelu_exact(u)));
        }
        __syncwarp();

        // ---- mm1: [16 x 160] @ [160 x 128] on tensor cores ----
        float D1[NNT][4];
        #pragma unroll
        for (int nt = 0; nt < NNT; nt++) { D1[nt][0]=0.f; D1[nt][1]=0.f; D1[nt][2]=0.f; D1[nt][3]=0.f; }

        for (int kt = 0; kt < NKT1; kt++) {
            const int k0 = kt * 8;
            const unsigned a0 = __float_as_uint(xw[swx(gid,     k0 + tig)]);
            const unsigned a1 = __float_as_uint(xw[swx(gid + 8, k0 + tig)]);
            const unsigned a2 = __float_as_uint(xw[swx(gid,     k0 + tig + 4)]);
            const unsigned a3 = __float_as_uint(xw[swx(gid + 8, k0 + tig + 4)]);
            #pragma unroll
            for (int h = 0; h < 2; h++) {
                uint2 bb[8];
                #pragma unroll
                for (int j = 0; j < 8; j++) bb[j] = wp1[(kt * NNT + h * 8 + j) * 32 + lane];
                #pragma unroll
                for (int j = 0; j < 8; j++) mma8(D1[h * 8 + j], a0, a1, a2, a3, bb[j]);
            }
        }

        // ---- ep1: +bias, LN1 (stats on fragments), GELU, store tf32 back ----
        float s0 = 0.f, q0 = 0.f, s1 = 0.f, q1 = 0.f;
        #pragma unroll
        for (int nt = 0; nt < NNT; nt++) {
            const int c = nt * 8 + 2 * tig;
            const float2 bb = *(const float2*)(spar + c);
            D1[nt][0] += bb.x; D1[nt][1] += bb.y; D1[nt][2] += bb.x; D1[nt][3] += bb.y;
            s0 += D1[nt][0] + D1[nt][1]; q0 += D1[nt][0]*D1[nt][0] + D1[nt][1]*D1[nt][1];
            s1 += D1[nt][2] + D1[nt][3]; q1 += D1[nt][2]*D1[nt][2] + D1[nt][3]*D1[nt][3];
        }
        s0 = tig_sum(s0); q0 = tig_sum(q0); s1 = tig_sum(s1); q1 = tig_sum(q1);
        const float m0 = s0 * (1.0f / DD), rs0 = rsqrtf(q0 * (1.0f / DD) - m0 * m0 + 1e-5f);
        const float m1 = s1 * (1.0f / DD), rs1 = rsqrtf(q1 * (1.0f / DD) - m1 * m1 + 1e-5f);
        #pragma unroll
        for (int nt = 0; nt < NNT; nt++) {
            const int c = nt * 8 + 2 * tig;
            const float2 lw = *(const float2*)(spar + DD + c);
            const float2 lb = *(const float2*)(spar + 2 * DD + c);
            float g0 = gelu_exact((D1[nt][0] - m0) * rs0 * lw.x + lb.x);
            float g1 = gelu_exact((D1[nt][1] - m0) * rs0 * lw.y + lb.y);
            float g2 = gelu_exact((D1[nt][2] - m1) * rs1 * lw.x + lb.x);
            float g3 = gelu_exact((D1[nt][3] - m1) * rs1 * lw.y + lb.y);
            float2 v0, v1;
            v0.x = __uint_as_float(tf32_bits(g0)); v0.y = __uint_as_float(tf32_bits(g1));
            v1.x = __uint_as_float(tf32_bits(g2)); v1.y = __uint_as_float(tf32_bits(g3));
            *(float2*)(xw + swx(gid,     c)) = v0;
            *(float2*)(xw + swx(gid + 8, c)) = v1;
        }
        __syncwarp();

        // ---- mm2: A frags into registers, then 16 n-tiles ----
        unsigned A2[NKT2][4];
        #pragma unroll
        for (int kt = 0; kt < NKT2; kt++) {
            const int k0 = kt * 8;
            A2[kt][0] = __float_as_uint(xw[swx(gid,     k0 + tig)]);
            A2[kt][1] = __float_as_uint(xw[swx(gid + 8, k0 + tig)]);
            A2[kt][2] = __float_as_uint(xw[swx(gid,     k0 + tig + 4)]);
            A2[kt][3] = __float_as_uint(xw[swx(gid + 8, k0 + tig + 4)]);
        }
        __syncwarp();

        float s20 = 0.f, q20 = 0.f, s21 = 0.f, q21 = 0.f;
        for (int nt = 0; nt < NNT; nt++) {
            float D2[4] = {0.f, 0.f, 0.f, 0.f};
            #pragma unroll
            for (int h = 0; h < 2; h++) {
                uint2 bb[8];
                #pragma unroll
                for (int j = 0; j < 8; j++) bb[j] = wp2[((h * 8 + j) * NNT + nt) * 32 + lane];
                #pragma unroll
                for (int j = 0; j < 8; j++) mma8(D2, A2[h*8+j][0], A2[h*8+j][1], A2[h*8+j][2], A2[h*8+j][3], bb[j]);
            }
            const int c = nt * 8 + 2 * tig;
            const float2 b2v = *(const float2*)(spar + 3 * DD + c);
            D2[0] += b2v.x; D2[1] += b2v.y; D2[2] += b2v.x; D2[3] += b2v.y;
            s20 += D2[0] + D2[1]; q20 += D2[0]*D2[0] + D2[1]*D2[1];
            s21 += D2[2] + D2[3]; q21 += D2[2]*D2[2] + D2[3]*D2[3];
            *(float2*)(xw + swx(gid,     c)) = make_float2(D2[0], D2[1]);
            *(float2*)(xw + swx(gid + 8, c)) = make_float2(D2[2], D2[3]);
        }
        s20 = tig_sum(s20); q20 = tig_sum(q20); s21 = tig_sum(s21); q21 = tig_sum(q21);
        const float mm0 = s20 * (1.0f / DD), rr0 = rsqrtf(q20 * (1.0f / DD) - mm0 * mm0 + 1e-5f);
        const float mm1v = s21 * (1.0f / DD), rr1 = rsqrtf(q21 * (1.0f / DD) - mm1v * mm1v + 1e-5f);
        __syncwarp();

        // ---- LN2 + masked pooling; stats broadcast via shfl ----
        #pragma unroll
        for (int t = 0; t < TOK; t++) {
            const float mt  = __shfl_sync(0xffffffffu, (t < 8) ? mm0 : mm1v, (t & 7) << 2);
            const float rst = __shfl_sync(0xffffffffu, (t < 8) ? rr0 : rr1,  (t & 7) << 2);
            if (l0 + t < len) {
                const float4 v = ld4(xw + swx(t, f4));
                pool.x += (v.x - mt) * rst * pl2w.x + pl2b.x;
                pool.y += (v.y - mt) * rst * pl2w.y + pl2b.y;
                pool.z += (v.z - mt) * rst * pl2w.z + pl2b.z;
                pool.w += (v.w - mt) * rst * pl2w.w + pl2b.w;
            }
        }
        __syncwarp();
    }

    // ---- direct output: lane owns features f4..f4+3 of this row ----
    float4 o;
    if (len > 0) {
        const float inv = 1.0f / (float)len;
        o = make_float4(pool.x * inv, pool.y * inv, pool.z * inv, pool.w * inv);
    } else {
        o = make_float4(0.f, 0.f, 0.f, 0.f);
    }
    *(float4*)(out + row * DD + f4) = o;
}

extern "C" void kernel_launch(void* const* d_in, const int* in_sizes, int n_in,
                              void* d_out, int out_size)
{
    const int*   ids     = (const int*)  d_in[0];
    const float* dates   = (const float*)d_in[1];
    const int*   lengths = (const int*)  d_in[2];
    const float* emb     = (const float*)d_in[3];
    const float* tp_w    = (const float*)d_in[4];
    const float* tp_b    = (const float*)d_in[5];
    const float* tp_lnw  = (const float*)d_in[6];
    const float* tp_lnb  = (const float*)d_in[7];
    const float* w1      = (const float*)d_in[8];
    const float* b1      = (const float*)d_in[9];
    const float* ln1w    = (const float*)d_in[10];
    const float* ln1b    = (const float*)d_in[11];
    const float* w2      = (const float*)d_in[12];
    const float* b2      = (const float*)d_in[13];
    const float* ln2w    = (const float*)d_in[14];
    const float* ln2b    = (const float*)d_in[15];
    float* out = (float*)d_out;

    const int B = in_sizes[2];            // 4096
    const int L = in_sizes[0] / B;        // 200

    pack_kernel<<<(WPN + 255) / 256, 256>>>(w1, w2);

    const size_t smem_bytes = (size_t)WPN * 8 + (size_t)(NW * TOK * 160 + 4 * DD) * sizeof(float);
    cudaFuncSetAttribute(tee_mma, cudaFuncAttributeMaxDynamicSharedMemorySize, (int)smem_bytes);
    const int grid = (B + NW - 1) / NW;
    tee_mma<<<grid, BD, smem_bytes>>>(ids, dates, lengths, emb,
                                      tp_w, tp_b, tp_lnw, tp_lnb,
                                      b1, ln1w, ln1b, b2, ln2w, ln2b,
                                      out, B, L);
}

// round 13
// speedup vs baseline: 2.9641x; 1.4731x over previous
#include <cuda_runtime.h>
#include <math.h>

#define BD   256
#define NW   8            // warps per CTA
#define DD   128
#define K1   160
#define TD   32
#define TOK  16
#define NKT1 20           // mm1 k-tiles (160/8)
#define NKT2 16           // mm2 k-tiles (128/8)
#define NNT  16           // n-tiles (128/8)
#define WPN  ((NKT1 + NKT2) * NNT * 32)   // total packed uint2 frags
#define GRID 148          // persistent: 1 CTA per SM

// fragment-packed weights, tf32 bit patterns: [kt][nt][lane] -> (b0,b1)
__device__ uint2 g_wp[WPN];
__device__ unsigned g_ctr;            // dynamic row counter (reset by pack kernel)

__device__ __forceinline__ unsigned tf32_bits(float f) {
    unsigned u; asm("cvt.rna.tf32.f32 %0, %1;" : "=r"(u) : "f"(f)); return u;
}
__device__ __forceinline__ float4 ld4(const float* p) { return *(const float4*)p; }

__device__ __forceinline__ void mma8(float* d, unsigned a0, unsigned a1,
                                     unsigned a2, unsigned a3, uint2 b) {
    asm volatile(
        "mma.sync.aligned.m16n8k8.row.col.f32.tf32.tf32.f32 "
        "{%0,%1,%2,%3}, {%4,%5,%6,%7}, {%8,%9}, {%0,%1,%2,%3};"
        : "+f"(d[0]), "+f"(d[1]), "+f"(d[2]), "+f"(d[3])
        : "r"(a0), "r"(a1), "r"(a2), "r"(a3), "r"(b.x), "r"(b.y));
}

__device__ __forceinline__ float gelu_exact(float x) {
    return 0.5f * x * (1.0f + erff(x * 0.70710678118654752f));
}
__device__ __forceinline__ void warp_sum2(float& s, float& sq) {
    #pragma unroll
    for (int o = 16; o; o >>= 1) {
        s  += __shfl_xor_sync(0xffffffffu, s,  o);
        sq += __shfl_xor_sync(0xffffffffu, sq, o);
    }
}
__device__ __forceinline__ float tig_sum(float v) {
    v += __shfl_xor_sync(0xffffffffu, v, 1);
    v += __shfl_xor_sync(0xffffffffu, v, 2);
    return v;
}

// swizzled activation index: token t, feature k. stride 160; XOR keeps
// A-fragment LDS (fixed k, varying t=gid) on distinct banks.
__device__ __forceinline__ int swx(int t, int k) {
    return t * 160 + (k ^ ((t & 7) << 2));
}

// ---------------- pack kernel: weights -> fragment order, tf32; resets counter ----
__global__ void pack_kernel(const float* __restrict__ w1, const float* __restrict__ w2) {
    int i = blockIdx.x * blockDim.x + threadIdx.x;
    if (i == 0) g_ctr = 0;
    const int T1 = NKT1 * NNT * 32;
    const int T2 = NKT2 * NNT * 32;
    if (i < T1) {
        int lane = i & 31, nt = (i >> 5) % NNT, kt = (i >> 5) / NNT;
        int g = lane >> 2, t = lane & 3;
        uint2 u;
        u.x = tf32_bits(w1[(kt * 8 + t)     * DD + nt * 8 + g]);
        u.y = tf32_bits(w1[(kt * 8 + t + 4) * DD + nt * 8 + g]);
        g_wp[i] = u;
    } else if (i < T1 + T2) {
        int j = i - T1;
        int lane = j & 31, nt = (j >> 5) % NNT, kt = (j >> 5) / NNT;
        int g = lane >> 2, t = lane & 3;
        uint2 u;
        u.x = tf32_bits(w2[(kt * 8 + t)     * DD + nt * 8 + g]);
        u.y = tf32_bits(w2[(kt * 8 + t + 4) * DD + nt * 8 + g]);
        g_wp[i] = u;
    }
}

// ---------------- main kernel: persistent warps, dynamic row stealing ----------
__global__ __launch_bounds__(BD, 1)
void tee_mma(const int*   __restrict__ ids,
             const float* __restrict__ dates,
             const int*   __restrict__ lengths,
             const float* __restrict__ emb,
             const float* __restrict__ tp_w,  const float* __restrict__ tp_b,
             const float* __restrict__ tp_lnw, const float* __restrict__ tp_lnb,
             const float* __restrict__ b1,  const float* __restrict__ ln1w, const float* __restrict__ ln1b,
             const float* __restrict__ b2,  const float* __restrict__ ln2w, const float* __restrict__ ln2b,
             float* __restrict__ out, int B, int L)
{
    extern __shared__ float smem[];
    uint2* s_wp  = (uint2*)smem;                 // 147456 B packed weight frags
    float* sxb   = smem + WPN * 2;               // NW*TOK*160 floats (81920 B)
    float* spar  = sxb + NW * TOK * 160;         // 4*DD params (2048 B)

    const int tid  = threadIdx.x;
    const int warp = tid >> 5;
    const int lane = tid & 31;
    const int gid  = lane >> 2;    // row within m16 tile
    const int tig  = lane & 3;     // thread-in-group
    const int f4   = lane * 4;

    // stage packed weights + params into SMEM (once per persistent CTA)
    {
        const uint4* src = (const uint4*)g_wp;
        uint4* dst = (uint4*)s_wp;
        for (int i = tid; i < WPN / 2; i += BD) dst[i] = src[i];
    }
    if (tid < DD) {
        spar[tid]          = b1[tid];
        spar[DD + tid]     = ln1w[tid];
        spar[2 * DD + tid] = ln1b[tid];
        spar[3 * DD + tid] = b2[tid];
    }
    __syncthreads();

    const float tpw = tp_w[lane], tpb = tp_b[lane];
    const float tplw = tp_lnw[lane], tplb = tp_lnb[lane];
    const float4 pl2w = ld4(ln2w + f4), pl2b = ld4(ln2b + f4);

    float* xw = sxb + warp * (TOK * 160);
    const uint2* wp1 = s_wp;
    const uint2* wp2 = s_wp + NKT1 * NNT * 32;

    for (;;) {
        // ---- pop next row ----
        unsigned row;
        if (lane == 0) row = atomicAdd(&g_ctr, 1u);
        row = __shfl_sync(0xffffffffu, row, 0);
        if (row >= (unsigned)B) break;

        const int len = lengths[row];
        float4 pool = make_float4(0.f, 0.f, 0.f, 0.f);

        const int ngroups = (len + TOK - 1) / TOK;
        for (int gi = 0; gi < ngroups; gi++) {
            const int l0 = gi * TOK;

            // ---- coalesced group prefetch: lanes 0..15 fetch ids/dates ----
            int   idv = 0;
            float dtv = 0.f;
            if (lane < TOK) {
                const int l = min(l0 + lane, L - 1);
                idv = ids[row * L + l];
                dtv = dates[row * L + l];
            }

            // ---- stage: embedding gather (batched, MLP=16), tf32-rounded ----
            #pragma unroll
            for (int t = 0; t < TOK; t++) {
                const int id = __shfl_sync(0xffffffffu, idv, t);
                float4 e = ld4(emb + id * DD + f4);
                float4 ec;
                ec.x = __uint_as_float(tf32_bits(e.x));
                ec.y = __uint_as_float(tf32_bits(e.y));
                ec.z = __uint_as_float(tf32_bits(e.z));
                ec.w = __uint_as_float(tf32_bits(e.w));
                *(float4*)(xw + swx(t, f4)) = ec;
            }
            // ---- temporal branch: Linear(1->32) + LN + GELU per token ----
            #pragma unroll
            for (int t = 0; t < TOK; t++) {
                const float dn = __shfl_sync(0xffffffffu, dtv, t) * (1.0f / 1825.0f);
                const float v  = fmaf(dn, tpw, tpb);
                float s = v, q = v * v;
                warp_sum2(s, q);
                const float m  = s * (1.0f / TD);
                const float rs = rsqrtf(q * (1.0f / TD) - m * m + 1e-5f);
                const float u  = (v - m) * rs * tplw + tplb;
                xw[swx(t, DD + lane)] = __uint_as_float(tf32_bits(gelu_exact(u)));
            }
            __syncwarp();

            // ---- mm1: [16 x 160] @ [160 x 128] on tensor cores ----
            float D1[NNT][4];
            #pragma unroll
            for (int nt = 0; nt < NNT; nt++) { D1[nt][0]=0.f; D1[nt][1]=0.f; D1[nt][2]=0.f; D1[nt][3]=0.f; }

            for (int kt = 0; kt < NKT1; kt++) {
                const int k0 = kt * 8;
                const unsigned a0 = __float_as_uint(xw[swx(gid,     k0 + tig)]);
                const unsigned a1 = __float_as_uint(xw[swx(gid + 8, k0 + tig)]);
                const unsigned a2 = __float_as_uint(xw[swx(gid,     k0 + tig + 4)]);
                const unsigned a3 = __float_as_uint(xw[swx(gid + 8, k0 + tig + 4)]);
                #pragma unroll
                for (int h = 0; h < 2; h++) {
                    uint2 bb[8];
                    #pragma unroll
                    for (int j = 0; j < 8; j++) bb[j] = wp1[(kt * NNT + h * 8 + j) * 32 + lane];
                    #pragma unroll
                    for (int j = 0; j < 8; j++) mma8(D1[h * 8 + j], a0, a1, a2, a3, bb[j]);
                }
            }

            // ---- ep1: +bias, LN1 (stats on fragments), GELU, store tf32 back ----
            float s0 = 0.f, q0 = 0.f, s1 = 0.f, q1 = 0.f;
            #pragma unroll
            for (int nt = 0; nt < NNT; nt++) {
                const int c = nt * 8 + 2 * tig;
                const float2 bb = *(const float2*)(spar + c);
                D1[nt][0] += bb.x; D1[nt][1] += bb.y; D1[nt][2] += bb.x; D1[nt][3] += bb.y;
                s0 += D1[nt][0] + D1[nt][1]; q0 += D1[nt][0]*D1[nt][0] + D1[nt][1]*D1[nt][1];
                s1 += D1[nt][2] + D1[nt][3]; q1 += D1[nt][2]*D1[nt][2] + D1[nt][3]*D1[nt][3];
            }
            s0 = tig_sum(s0); q0 = tig_sum(q0); s1 = tig_sum(s1); q1 = tig_sum(q1);
            const float m0 = s0 * (1.0f / DD), rs0 = rsqrtf(q0 * (1.0f / DD) - m0 * m0 + 1e-5f);
            const float m1 = s1 * (1.0f / DD), rs1 = rsqrtf(q1 * (1.0f / DD) - m1 * m1 + 1e-5f);
            #pragma unroll
            for (int nt = 0; nt < NNT; nt++) {
                const int c = nt * 8 + 2 * tig;
                const float2 lw = *(const float2*)(spar + DD + c);
                const float2 lb = *(const float2*)(spar + 2 * DD + c);
                float g0 = gelu_exact((D1[nt][0] - m0) * rs0 * lw.x + lb.x);
                float g1 = gelu_exact((D1[nt][1] - m0) * rs0 * lw.y + lb.y);
                float g2 = gelu_exact((D1[nt][2] - m1) * rs1 * lw.x + lb.x);
                float g3 = gelu_exact((D1[nt][3] - m1) * rs1 * lw.y + lb.y);
                float2 v0, v1;
                v0.x = __uint_as_float(tf32_bits(g0)); v0.y = __uint_as_float(tf32_bits(g1));
                v1.x = __uint_as_float(tf32_bits(g2)); v1.y = __uint_as_float(tf32_bits(g3));
                *(float2*)(xw + swx(gid,     c)) = v0;
                *(float2*)(xw + swx(gid + 8, c)) = v1;
            }
            __syncwarp();

            // ---- mm2: A frags into registers, then 16 n-tiles ----
            unsigned A2[NKT2][4];
            #pragma unroll
            for (int kt = 0; kt < NKT2; kt++) {
                const int k0 = kt * 8;
                A2[kt][0] = __float_as_uint(xw[swx(gid,     k0 + tig)]);
                A2[kt][1] = __float_as_uint(xw[swx(gid + 8, k0 + tig)]);
                A2[kt][2] = __float_as_uint(xw[swx(gid,     k0 + tig + 4)]);
                A2[kt][3] = __float_as_uint(xw[swx(gid + 8, k0 + tig + 4)]);
            }
            __syncwarp();

            float s20 = 0.f, q20 = 0.f, s21 = 0.f, q21 = 0.f;
            for (int nt = 0; nt < NNT; nt++) {
                float D2[4] = {0.f, 0.f, 0.f, 0.f};
                #pragma unroll
                for (int h = 0; h < 2; h++) {
                    uint2 bb[8];
                    #pragma unroll
                    for (int j = 0; j < 8; j++) bb[j] = wp2[((h * 8 + j) * NNT + nt) * 32 + lane];
                    #pragma unroll
                    for (int j = 0; j < 8; j++) mma8(D2, A2[h*8+j][0], A2[h*8+j][1], A2[h*8+j][2], A2[h*8+j][3], bb[j]);
                }
                const int c = nt * 8 + 2 * tig;
                const float2 b2v = *(const float2*)(spar + 3 * DD + c);
                D2[0] += b2v.x; D2[1] += b2v.y; D2[2] += b2v.x; D2[3] += b2v.y;
                s20 += D2[0] + D2[1]; q20 += D2[0]*D2[0] + D2[1]*D2[1];
                s21 += D2[2] + D2[3]; q21 += D2[2]*D2[2] + D2[3]*D2[3];
                *(float2*)(xw + swx(gid,     c)) = make_float2(D2[0], D2[1]);
                *(float2*)(xw + swx(gid + 8, c)) = make_float2(D2[2], D2[3]);
            }
            s20 = tig_sum(s20); q20 = tig_sum(q20); s21 = tig_sum(s21); q21 = tig_sum(q21);
            const float mm0 = s20 * (1.0f / DD), rr0 = rsqrtf(q20 * (1.0f / DD) - mm0 * mm0 + 1e-5f);
            const float mm1v = s21 * (1.0f / DD), rr1 = rsqrtf(q21 * (1.0f / DD) - mm1v * mm1v + 1e-5f);
            __syncwarp();

            // ---- LN2 + masked pooling; stats broadcast via shfl ----
            #pragma unroll
            for (int t = 0; t < TOK; t++) {
                const float mt  = __shfl_sync(0xffffffffu, (t < 8) ? mm0 : mm1v, (t & 7) << 2);
                const float rst = __shfl_sync(0xffffffffu, (t < 8) ? rr0 : rr1,  (t & 7) << 2);
                if (l0 + t < len) {
                    const float4 v = ld4(xw + swx(t, f4));
                    pool.x += (v.x - mt) * rst * pl2w.x + pl2b.x;
                    pool.y += (v.y - mt) * rst * pl2w.y + pl2b.y;
                    pool.z += (v.z - mt) * rst * pl2w.z + pl2b.z;
                    pool.w += (v.w - mt) * rst * pl2w.w + pl2b.w;
                }
            }
            __syncwarp();
        }

        // ---- direct output: lane owns features f4..f4+3 of this row ----
        float4 o;
        if (len > 0) {
            const float inv = 1.0f / (float)len;
            o = make_float4(pool.x * inv, pool.y * inv, pool.z * inv, pool.w * inv);
        } else {
            o = make_float4(0.f, 0.f, 0.f, 0.f);
        }
        *(float4*)(out + row * DD + f4) = o;
    }
}

extern "C" void kernel_launch(void* const* d_in, const int* in_sizes, int n_in,
                              void* d_out, int out_size)
{
    const int*   ids     = (const int*)  d_in[0];
    const float* dates   = (const float*)d_in[1];
    const int*   lengths = (const int*)  d_in[2];
    const float* emb     = (const float*)d_in[3];
    const float* tp_w    = (const float*)d_in[4];
    const float* tp_b    = (const float*)d_in[5];
    const float* tp_lnw  = (const float*)d_in[6];
    const float* tp_lnb  = (const float*)d_in[7];
    const float* w1      = (const float*)d_in[8];
    const float* b1      = (const float*)d_in[9];
    const float* ln1w    = (const float*)d_in[10];
    const float* ln1b    = (const float*)d_in[11];
    const float* w2      = (const float*)d_in[12];
    const float* b2      = (const float*)d_in[13];
    const float* ln2w    = (const float*)d_in[14];
    const float* ln2b    = (const float*)d_in[15];
    float* out = (float*)d_out;

    const int B = in_sizes[2];            // 4096
    const int L = in_sizes[0] / B;        // 200

    pack_kernel<<<(WPN + 255) / 256, 256>>>(w1, w2);   // also resets g_ctr

    const size_t smem_bytes = (size_t)WPN * 8 + (size_t)(NW * TOK * 160 + 4 * DD) * sizeof(float);
    cudaFuncSetAttribute(tee_mma, cudaFuncAttributeMaxDynamicSharedMemorySize, (int)smem_bytes);
    tee_mma<<<GRID, BD, smem_bytes>>>(ids, dates, lengths, emb,
                                      tp_w, tp_b, tp_lnw, tp_lnb,
                                      b1, ln1w, ln1b, b2, ln2w, ln2b,
                                      out, B, L);
}

// round 14
// speedup vs baseline: 2.9872x; 1.0078x over previous
#include <cuda_runtime.h>
#include <math.h>

#define BD   256
#define NW   8            // warps per CTA
#define DD   128
#define K1   160
#define TD   32
#define TOK  16
#define NKT1 20           // mm1 k-tiles (160/8)
#define NKT2 16           // mm2 k-tiles (128/8)
#define NNT  16           // n-tiles (128/8)
#define Q1N  (NKT1 * 2 * 4 * 32)          // mm1 packed uint4 count (5120)
#define Q2N  (NKT2 * 2 * 4 * 32)          // mm2 packed uint4 count (4096)
#define QTOT (Q1N + Q2N)                  // 9216 uint4 = 147456 B
#define GRID 148          // persistent: 1 CTA per SM

// fragment-PAIR-packed weights (uint4 = two tf32 B-fragments per lane)
__device__ uint4 g_wp[QTOT];
__device__ unsigned g_ctr;            // dynamic row counter (reset by pack kernel)

__device__ __forceinline__ unsigned tf32_bits(float f) {
    unsigned u; asm("cvt.rna.tf32.f32 %0, %1;" : "=r"(u) : "f"(f)); return u;
}
__device__ __forceinline__ float4 ld4(const float* p) { return *(const float4*)p; }

__device__ __forceinline__ void mma8(float* d, unsigned a0, unsigned a1,
                                     unsigned a2, unsigned a3, unsigned bx, unsigned by) {
    asm volatile(
        "mma.sync.aligned.m16n8k8.row.col.f32.tf32.tf32.f32 "
        "{%0,%1,%2,%3}, {%4,%5,%6,%7}, {%8,%9}, {%0,%1,%2,%3};"
        : "+f"(d[0]), "+f"(d[1]), "+f"(d[2]), "+f"(d[3])
        : "r"(a0), "r"(a1), "r"(a2), "r"(a3), "r"(bx), "r"(by));
}

__device__ __forceinline__ float gelu_exact(float x) {
    return 0.5f * x * (1.0f + erff(x * 0.70710678118654752f));
}
__device__ __forceinline__ void warp_sum2(float& s, float& sq) {
    #pragma unroll
    for (int o = 16; o; o >>= 1) {
        s  += __shfl_xor_sync(0xffffffffu, s,  o);
        sq += __shfl_xor_sync(0xffffffffu, sq, o);
    }
}
__device__ __forceinline__ float tig_sum(float v) {
    v += __shfl_xor_sync(0xffffffffu, v, 1);
    v += __shfl_xor_sync(0xffffffffu, v, 2);
    return v;
}

// swizzled activation index: token t, feature k. stride 160; XOR keeps
// A-fragment LDS (fixed k, varying t=gid) on distinct banks.
__device__ __forceinline__ int swx(int t, int k) {
    return t * 160 + (k ^ ((t & 7) << 2));
}

// ---------------- pack kernel: weights -> paired fragment order, tf32 --------
// mm1 layout: uint4 index ((kt*2+h)*4 + jp)*32 + lane holds frags nt=h*8+2jp, +1
// mm2 layout: uint4 index Q1N + ((nt*2+h)*4 + jp)*32 + lane holds frags kt=h*8+2jp, +1
__global__ void pack_kernel(const float* __restrict__ w1, const float* __restrict__ w2) {
    int i = blockIdx.x * blockDim.x + threadIdx.x;
    if (i == 0) g_ctr = 0;
    if (i < Q1N) {
        const int lane = i & 31, jp = (i >> 5) & 3, g = i >> 7;
        const int h = g & 1, kt = g >> 1;
        const int nc = lane >> 2, t = lane & 3;
        const int nt0 = h * 8 + 2 * jp;
        uint4 u;
        u.x = tf32_bits(w1[(kt * 8 + t)     * DD + nt0 * 8 + nc]);
        u.y = tf32_bits(w1[(kt * 8 + t + 4) * DD + nt0 * 8 + nc]);
        u.z = tf32_bits(w1[(kt * 8 + t)     * DD + (nt0 + 1) * 8 + nc]);
        u.w = tf32_bits(w1[(kt * 8 + t + 4) * DD + (nt0 + 1) * 8 + nc]);
        g_wp[i] = u;
    } else if (i < QTOT) {
        const int j = i - Q1N;
        const int lane = j & 31, jp = (j >> 5) & 3, g = j >> 7;
        const int h = g & 1, nt = g >> 1;
        const int nc = lane >> 2, t = lane & 3;
        const int kt0 = h * 8 + 2 * jp;
        uint4 u;
        u.x = tf32_bits(w2[(kt0 * 8 + t)           * DD + nt * 8 + nc]);
        u.y = tf32_bits(w2[(kt0 * 8 + t + 4)       * DD + nt * 8 + nc]);
        u.z = tf32_bits(w2[((kt0 + 1) * 8 + t)     * DD + nt * 8 + nc]);
        u.w = tf32_bits(w2[((kt0 + 1) * 8 + t + 4) * DD + nt * 8 + nc]);
        g_wp[i] = u;
    }
}

// ---------------- main kernel: persistent warps, dynamic row stealing ----------
__global__ __launch_bounds__(BD, 1)
void tee_mma(const int*   __restrict__ ids,
             const float* __restrict__ dates,
             const int*   __restrict__ lengths,
             const float* __restrict__ emb,
             const float* __restrict__ tp_w,  const float* __restrict__ tp_b,
             const float* __restrict__ tp_lnw, const float* __restrict__ tp_lnb,
             const float* __restrict__ b1,  const float* __restrict__ ln1w, const float* __restrict__ ln1b,
             const float* __restrict__ b2,  const float* __restrict__ ln2w, const float* __restrict__ ln2b,
             float* __restrict__ out, int B, int L)
{
    extern __shared__ float smem[];
    uint4* s_wp  = (uint4*)smem;                 // 147456 B packed weight frag pairs
    float* sxb   = smem + QTOT * 4;              // NW*TOK*160 floats (81920 B)
    float* spar  = sxb + NW * TOK * 160;         // 4*DD params (2048 B)

    const int tid  = threadIdx.x;
    const int warp = tid >> 5;
    const int lane = tid & 31;
    const int gid  = lane >> 2;    // row within m16 tile
    const int tig  = lane & 3;     // thread-in-group
    const int f4   = lane * 4;

    // stage packed weights + params into SMEM (once per persistent CTA)
    for (int i = tid; i < QTOT; i += BD) s_wp[i] = g_wp[i];
    if (tid < DD) {
        spar[tid]          = b1[tid];
        spar[DD + tid]     = ln1w[tid];
        spar[2 * DD + tid] = ln1b[tid];
        spar[3 * DD + tid] = b2[tid];
    }
    __syncthreads();

    const float tpw = tp_w[lane], tpb = tp_b[lane];
    const float tplw = tp_lnw[lane], tplb = tp_lnb[lane];
    const float4 pl2w = ld4(ln2w + f4), pl2b = ld4(ln2b + f4);

    float* xw = sxb + warp * (TOK * 160);
    const uint4* wp1 = s_wp;
    const uint4* wp2 = s_wp + Q1N;

    for (;;) {
        // ---- pop next row ----
        unsigned row;
        if (lane == 0) row = atomicAdd(&g_ctr, 1u);
        row = __shfl_sync(0xffffffffu, row, 0);
        if (row >= (unsigned)B) break;

        const int len = lengths[row];
        float4 pool = make_float4(0.f, 0.f, 0.f, 0.f);

        const int ngroups = (len + TOK - 1) / TOK;
        for (int gi = 0; gi < ngroups; gi++) {
            const int l0 = gi * TOK;

            // ---- coalesced group prefetch: lanes 0..15 fetch ids/dates ----
            int   idv = 0;
            float dtv = 0.f;
            if (lane < TOK) {
                const int l = min(l0 + lane, L - 1);
                idv = ids[row * L + l];
                dtv = dates[row * L + l];
            }

            // ---- stage: embedding gather (batched, MLP=16), tf32-rounded ----
            #pragma unroll
            for (int t = 0; t < TOK; t++) {
                const int id = __shfl_sync(0xffffffffu, idv, t);
                float4 e = ld4(emb + id * DD + f4);
                float4 ec;
                ec.x = __uint_as_float(tf32_bits(e.x));
                ec.y = __uint_as_float(tf32_bits(e.y));
                ec.z = __uint_as_float(tf32_bits(e.z));
                ec.w = __uint_as_float(tf32_bits(e.w));
                *(float4*)(xw + swx(t, f4)) = ec;
            }
            // ---- temporal branch: Linear(1->32) + LN + GELU per token ----
            #pragma unroll
            for (int t = 0; t < TOK; t++) {
                const float dn = __shfl_sync(0xffffffffu, dtv, t) * (1.0f / 1825.0f);
                const float v  = fmaf(dn, tpw, tpb);
                float s = v, q = v * v;
                warp_sum2(s, q);
                const float m  = s * (1.0f / TD);
                const float rs = rsqrtf(q * (1.0f / TD) - m * m + 1e-5f);
                const float u  = (v - m) * rs * tplw + tplb;
                xw[swx(t, DD + lane)] = __uint_as_float(tf32_bits(gelu_exact(u)));
            }
            __syncwarp();

            // ---- mm1: [16 x 160] @ [160 x 128]; 4x LDS.128 per 8-mma batch ----
            float D1[NNT][4];
            #pragma unroll
            for (int nt = 0; nt < NNT; nt++) { D1[nt][0]=0.f; D1[nt][1]=0.f; D1[nt][2]=0.f; D1[nt][3]=0.f; }

            for (int kt = 0; kt < NKT1; kt++) {
                const int k0 = kt * 8;
                const unsigned a0 = __float_as_uint(xw[swx(gid,     k0 + tig)]);
                const unsigned a1 = __float_as_uint(xw[swx(gid + 8, k0 + tig)]);
                const unsigned a2 = __float_as_uint(xw[swx(gid,     k0 + tig + 4)]);
                const unsigned a3 = __float_as_uint(xw[swx(gid + 8, k0 + tig + 4)]);
                #pragma unroll
                for (int h = 0; h < 2; h++) {
                    const uint4* base = wp1 + ((kt * 2 + h) * 4) * 32 + lane;
                    uint4 q0 = base[0], q1 = base[32], q2 = base[64], q3 = base[96];
                    mma8(D1[h*8+0], a0, a1, a2, a3, q0.x, q0.y);
                    mma8(D1[h*8+1], a0, a1, a2, a3, q0.z, q0.w);
                    mma8(D1[h*8+2], a0, a1, a2, a3, q1.x, q1.y);
                    mma8(D1[h*8+3], a0, a1, a2, a3, q1.z, q1.w);
                    mma8(D1[h*8+4], a0, a1, a2, a3, q2.x, q2.y);
                    mma8(D1[h*8+5], a0, a1, a2, a3, q2.z, q2.w);
                    mma8(D1[h*8+6], a0, a1, a2, a3, q3.x, q3.y);
                    mma8(D1[h*8+7], a0, a1, a2, a3, q3.z, q3.w);
                }
            }

            // ---- ep1: +bias, LN1 (stats on fragments), GELU, store tf32 back ----
            float s0 = 0.f, q0s = 0.f, s1 = 0.f, q1s = 0.f;
            #pragma unroll
            for (int nt = 0; nt < NNT; nt++) {
                const int c = nt * 8 + 2 * tig;
                const float2 bb = *(const float2*)(spar + c);
                D1[nt][0] += bb.x; D1[nt][1] += bb.y; D1[nt][2] += bb.x; D1[nt][3] += bb.y;
                s0 += D1[nt][0] + D1[nt][1]; q0s += D1[nt][0]*D1[nt][0] + D1[nt][1]*D1[nt][1];
                s1 += D1[nt][2] + D1[nt][3]; q1s += D1[nt][2]*D1[nt][2] + D1[nt][3]*D1[nt][3];
            }
            s0 = tig_sum(s0); q0s = tig_sum(q0s); s1 = tig_sum(s1); q1s = tig_sum(q1s);
            const float m0 = s0 * (1.0f / DD), rs0 = rsqrtf(q0s * (1.0f / DD) - m0 * m0 + 1e-5f);
            const float m1 = s1 * (1.0f / DD), rs1 = rsqrtf(q1s * (1.0f / DD) - m1 * m1 + 1e-5f);
            #pragma unroll
            for (int nt = 0; nt < NNT; nt++) {
                const int c = nt * 8 + 2 * tig;
                const float2 lw = *(const float2*)(spar + DD + c);
                const float2 lb = *(const float2*)(spar + 2 * DD + c);
                float g0 = gelu_exact((D1[nt][0] - m0) * rs0 * lw.x + lb.x);
                float g1 = gelu_exact((D1[nt][1] - m0) * rs0 * lw.y + lb.y);
                float g2 = gelu_exact((D1[nt][2] - m1) * rs1 * lw.x + lb.x);
                float g3 = gelu_exact((D1[nt][3] - m1) * rs1 * lw.y + lb.y);
                float2 v0, v1;
                v0.x = __uint_as_float(tf32_bits(g0)); v0.y = __uint_as_float(tf32_bits(g1));
                v1.x = __uint_as_float(tf32_bits(g2)); v1.y = __uint_as_float(tf32_bits(g3));
                *(float2*)(xw + swx(gid,     c)) = v0;
                *(float2*)(xw + swx(gid + 8, c)) = v1;
            }
            __syncwarp();

            // ---- mm2: A frags into registers, then 16 n-tiles ----
            unsigned A2[NKT2][4];
            #pragma unroll
            for (int kt = 0; kt < NKT2; kt++) {
                const int k0 = kt * 8;
                A2[kt][0] = __float_as_uint(xw[swx(gid,     k0 + tig)]);
                A2[kt][1] = __float_as_uint(xw[swx(gid + 8, k0 + tig)]);
                A2[kt][2] = __float_as_uint(xw[swx(gid,     k0 + tig + 4)]);
                A2[kt][3] = __float_as_uint(xw[swx(gid + 8, k0 + tig + 4)]);
            }
            __syncwarp();

            float s20 = 0.f, q20 = 0.f, s21 = 0.f, q21 = 0.f;
            for (int nt = 0; nt < NNT; nt++) {
                float D2[4] = {0.f, 0.f, 0.f, 0.f};
                #pragma unroll
                for (int h = 0; h < 2; h++) {
                    const uint4* base = wp2 + ((nt * 2 + h) * 4) * 32 + lane;
                    uint4 q0 = base[0], q1 = base[32], q2 = base[64], q3 = base[96];
                    const int kb = h * 8;
                    mma8(D2, A2[kb+0][0], A2[kb+0][1], A2[kb+0][2], A2[kb+0][3], q0.x, q0.y);
                    mma8(D2, A2[kb+1][0], A2[kb+1][1], A2[kb+1][2], A2[kb+1][3], q0.z, q0.w);
                    mma8(D2, A2[kb+2][0], A2[kb+2][1], A2[kb+2][2], A2[kb+2][3], q1.x, q1.y);
                    mma8(D2, A2[kb+3][0], A2[kb+3][1], A2[kb+3][2], A2[kb+3][3], q1.z, q1.w);
                    mma8(D2, A2[kb+4][0], A2[kb+4][1], A2[kb+4][2], A2[kb+4][3], q2.x, q2.y);
                    mma8(D2, A2[kb+5][0], A2[kb+5][1], A2[kb+5][2], A2[kb+5][3], q2.z, q2.w);
                    mma8(D2, A2[kb+6][0], A2[kb+6][1], A2[kb+6][2], A2[kb+6][3], q3.x, q3.y);
                    mma8(D2, A2[kb+7][0], A2[kb+7][1], A2[kb+7][2], A2[kb+7][3], q3.z, q3.w);
                }
                const int c = nt * 8 + 2 * tig;
                const float2 b2v = *(const float2*)(spar + 3 * DD + c);
                D2[0] += b2v.x; D2[1] += b2v.y; D2[2] += b2v.x; D2[3] += b2v.y;
                s20 += D2[0] + D2[1]; q20 += D2[0]*D2[0] + D2[1]*D2[1];
                s21 += D2[2] + D2[3]; q21 += D2[2]*D2[2] + D2[3]*D2[3];
                *(float2*)(xw + swx(gid,     c)) = make_float2(D2[0], D2[1]);
                *(float2*)(xw + swx(gid + 8, c)) = make_float2(D2[2], D2[3]);
            }
            s20 = tig_sum(s20); q20 = tig_sum(q20); s21 = tig_sum(s21); q21 = tig_sum(q21);
            const float mm0 = s20 * (1.0f / DD), rr0 = rsqrtf(q20 * (1.0f / DD) - mm0 * mm0 + 1e-5f);
            const float mm1v = s21 * (1.0f / DD), rr1 = rsqrtf(q21 * (1.0f / DD) - mm1v * mm1v + 1e-5f);
            __syncwarp();

            // ---- LN2 + masked pooling; stats broadcast via shfl ----
            #pragma unroll
            for (int t = 0; t < TOK; t++) {
                const float mt  = __shfl_sync(0xffffffffu, (t < 8) ? mm0 : mm1v, (t & 7) << 2);
                const float rst = __shfl_sync(0xffffffffu, (t < 8) ? rr0 : rr1,  (t & 7) << 2);
                if (l0 + t < len) {
                    const float4 v = ld4(xw + swx(t, f4));
                    pool.x += (v.x - mt) * rst * pl2w.x + pl2b.x;
                    pool.y += (v.y - mt) * rst * pl2w.y + pl2b.y;
                    pool.z += (v.z - mt) * rst * pl2w.z + pl2b.z;
                    pool.w += (v.w - mt) * rst * pl2w.w + pl2b.w;
                }
            }
            __syncwarp();
        }

        // ---- direct output: lane owns features f4..f4+3 of this row ----
        float4 o;
        if (len > 0) {
            const float inv = 1.0f / (float)len;
            o = make_float4(pool.x * inv, pool.y * inv, pool.z * inv, pool.w * inv);
        } else {
            o = make_float4(0.f, 0.f, 0.f, 0.f);
        }
        *(float4*)(out + row * DD + f4) = o;
    }
}

extern "C" void kernel_launch(void* const* d_in, const int* in_sizes, int n_in,
                              void* d_out, int out_size)
{
    const int*   ids     = (const int*)  d_in[0];
    const float* dates   = (const float*)d_in[1];
    const int*   lengths = (const int*)  d_in[2];
    const float* emb     = (const float*)d_in[3];
    const float* tp_w    = (const float*)d_in[4];
    const float* tp_b    = (const float*)d_in[5];
    const float* tp_lnw  = (const float*)d_in[6];
    const float* tp_lnb  = (const float*)d_in[7];
    const float* w1      = (const float*)d_in[8];
    const float* b1      = (const float*)d_in[9];
    const float* ln1w    = (const float*)d_in[10];
    const float* ln1b    = (const float*)d_in[11];
    const float* w2      = (const float*)d_in[12];
    const float* b2      = (const float*)d_in[13];
    const float* ln2w    = (const float*)d_in[14];
    const float* ln2b    = (const float*)d_in[15];
    float* out = (float*)d_out;

    const int B = in_sizes[2];            // 4096
    const int L = in_sizes[0] / B;        // 200

    pack_kernel<<<(QTOT + 255) / 256, 256>>>(w1, w2);   // also resets g_ctr

    const size_t smem_bytes = (size_t)QTOT * 16 + (size_t)(NW * TOK * 160 + 4 * DD) * sizeof(float);
    cudaFuncSetAttribute(tee_mma, cudaFuncAttributeMaxDynamicSharedMemorySize, (int)smem_bytes);
    tee_mma<<<GRID, BD, smem_bytes>>>(ids, dates, lengths, emb,
                                      tp_w, tp_b, tp_lnw, tp_lnb,
                                      b1, ln1w, ln1b, b2, ln2w, ln2b,
                                      out, B, L);
}

// round 15
// speedup vs baseline: 3.4832x; 1.1660x over previous
#include <cuda_runtime.h>
#include <math.h>

#define BD   256
#define NW   8            // warps per CTA
#define DD   128
#define K1   160
#define TD   32
#define TOK  16
#define NKT1 20           // mm1 k-tiles (160/8)
#define NKT2 16           // mm2 k-tiles (128/8)
#define NNT  16           // n-tiles (128/8)
#define Q1N  (NKT1 * 2 * 4 * 32)          // mm1 packed uint4 count (5120)
#define Q2N  (NKT2 * 2 * 4 * 32)          // mm2 packed uint4 count (4096)
#define QTOT (Q1N + Q2N)                  // 9216 uint4 = 147456 B
#define GRID 148          // persistent: 1 CTA per SM

// fragment-PAIR-packed weights (uint4 = two tf32 B-fragments per lane)
__device__ uint4 g_wp[QTOT];
__device__ unsigned g_ctr;            // dynamic row counter (reset by pack kernel)

__device__ __forceinline__ unsigned tf32_bits(float f) {
    unsigned u; asm("cvt.rna.tf32.f32 %0, %1;" : "=r"(u) : "f"(f)); return u;
}
__device__ __forceinline__ float4 ld4(const float* p) { return *(const float4*)p; }

__device__ __forceinline__ void mma8(float* d, unsigned a0, unsigned a1,
                                     unsigned a2, unsigned a3, unsigned bx, unsigned by) {
    asm volatile(
        "mma.sync.aligned.m16n8k8.row.col.f32.tf32.tf32.f32 "
        "{%0,%1,%2,%3}, {%4,%5,%6,%7}, {%8,%9}, {%0,%1,%2,%3};"
        : "+f"(d[0]), "+f"(d[1]), "+f"(d[2]), "+f"(d[3])
        : "r"(a0), "r"(a1), "r"(a2), "r"(a3), "r"(bx), "r"(by));
}

// HW tanh (MUFU.TANH, sm_75+): single-op GELU core
__device__ __forceinline__ float tanh_fast(float x) {
    float r; asm("tanh.approx.f32 %0, %1;" : "=f"(r) : "f"(x)); return r;
}
__device__ __forceinline__ float gelu_fast(float x) {
    const float x2 = x * x;
    const float p  = fmaf(0.044715f * x, x2, x);
    const float th = tanh_fast(0.79788456080286536f * p);
    const float hx = 0.5f * x;
    return fmaf(hx, th, hx);
}

__device__ __forceinline__ void warp_sum2(float& s, float& sq) {
    #pragma unroll
    for (int o = 16; o; o >>= 1) {
        s  += __shfl_xor_sync(0xffffffffu, s,  o);
        sq += __shfl_xor_sync(0xffffffffu, sq, o);
    }
}
__device__ __forceinline__ float tig_sum(float v) {
    v += __shfl_xor_sync(0xffffffffu, v, 1);
    v += __shfl_xor_sync(0xffffffffu, v, 2);
    return v;
}

// swizzled activation index: token t, feature k. stride 160; XOR keeps
// A-fragment LDS (fixed k, varying t=gid) on distinct banks.
__device__ __forceinline__ int swx(int t, int k) {
    return t * 160 + (k ^ ((t & 7) << 2));
}

// ---------------- pack kernel: weights -> paired fragment order, tf32 --------
__global__ void pack_kernel(const float* __restrict__ w1, const float* __restrict__ w2) {
    int i = blockIdx.x * blockDim.x + threadIdx.x;
    if (i == 0) g_ctr = 0;
    if (i < Q1N) {
        const int lane = i & 31, jp = (i >> 5) & 3, g = i >> 7;
        const int h = g & 1, kt = g >> 1;
        const int nc = lane >> 2, t = lane & 3;
        const int nt0 = h * 8 + 2 * jp;
        uint4 u;
        u.x = tf32_bits(w1[(kt * 8 + t)     * DD + nt0 * 8 + nc]);
        u.y = tf32_bits(w1[(kt * 8 + t + 4) * DD + nt0 * 8 + nc]);
        u.z = tf32_bits(w1[(kt * 8 + t)     * DD + (nt0 + 1) * 8 + nc]);
        u.w = tf32_bits(w1[(kt * 8 + t + 4) * DD + (nt0 + 1) * 8 + nc]);
        g_wp[i] = u;
    } else if (i < QTOT) {
        const int j = i - Q1N;
        const int lane = j & 31, jp = (j >> 5) & 3, g = j >> 7;
        const int h = g & 1, nt = g >> 1;
        const int nc = lane >> 2, t = lane & 3;
        const int kt0 = h * 8 + 2 * jp;
        uint4 u;
        u.x = tf32_bits(w2[(kt0 * 8 + t)           * DD + nt * 8 + nc]);
        u.y = tf32_bits(w2[(kt0 * 8 + t + 4)       * DD + nt * 8 + nc]);
        u.z = tf32_bits(w2[((kt0 + 1) * 8 + t)     * DD + nt * 8 + nc]);
        u.w = tf32_bits(w2[((kt0 + 1) * 8 + t + 4) * DD + nt * 8 + nc]);
        g_wp[i] = u;
    }
}

// ---------------- main kernel: persistent warps, dynamic row stealing ----------
__global__ __launch_bounds__(BD, 1)
void tee_mma(const int*   __restrict__ ids,
             const float* __restrict__ dates,
             const int*   __restrict__ lengths,
             const float* __restrict__ emb,
             const float* __restrict__ tp_w,  const float* __restrict__ tp_b,
             const float* __restrict__ tp_lnw, const float* __restrict__ tp_lnb,
             const float* __restrict__ b1,  const float* __restrict__ ln1w, const float* __restrict__ ln1b,
             const float* __restrict__ b2,  const float* __restrict__ ln2w, const float* __restrict__ ln2b,
             float* __restrict__ out, int B, int L)
{
    extern __shared__ float smem[];
    uint4* s_wp  = (uint4*)smem;                 // 147456 B packed weight frag pairs
    float* sxb   = smem + QTOT * 4;              // NW*TOK*160 floats (81920 B)
    float* spar  = sxb + NW * TOK * 160;         // 4*DD params (2048 B)

    const int tid  = threadIdx.x;
    const int warp = tid >> 5;
    const int lane = tid & 31;
    const int gid  = lane >> 2;    // row within m16 tile
    const int tig  = lane & 3;     // thread-in-group
    const int f4   = lane * 4;

    // stage packed weights + params into SMEM (once per persistent CTA)
    for (int i = tid; i < QTOT; i += BD) s_wp[i] = g_wp[i];
    if (tid < DD) {
        spar[tid]          = b1[tid];
        spar[DD + tid]     = ln1w[tid];
        spar[2 * DD + tid] = ln1b[tid];
        spar[3 * DD + tid] = b2[tid];
    }
    __syncthreads();

    const float tpw = tp_w[lane], tpb = tp_b[lane];
    const float tplw = tp_lnw[lane], tplb = tp_lnb[lane];
    const float4 pl2w = ld4(ln2w + f4), pl2b = ld4(ln2b + f4);

    float* xw = sxb + warp * (TOK * 160);
    const uint4* wp1 = s_wp;
    const uint4* wp2 = s_wp + Q1N;

    for (;;) {
        // ---- pop next row ----
        unsigned row;
        if (lane == 0) row = atomicAdd(&g_ctr, 1u);
        row = __shfl_sync(0xffffffffu, row, 0);
        if (row >= (unsigned)B) break;

        const int len = lengths[row];
        float4 pool = make_float4(0.f, 0.f, 0.f, 0.f);
        const int ngroups = (len + TOK - 1) / TOK;

        // ---- prefetch group 0 ids/dates ----
        int   idv = 0;
        float dtv = 0.f;
        if (ngroups > 0 && lane < TOK) {
            const int l = min(lane, L - 1);
            idv = ids[row * L + l];
            dtv = dates[row * L + l];
        }

        for (int gi = 0; gi < ngroups; gi++) {
            const int l0 = gi * TOK;
            const int   cid = idv;
            const float cdt = dtv;

            // ---- prefetch NEXT group's ids/dates (hidden under this group) ----
            if (gi + 1 < ngroups && lane < TOK) {
                const int l = min(l0 + TOK + lane, L - 1);
                idv = ids[row * L + l];
                dtv = dates[row * L + l];
            }

            // ---- stage: embedding gather (batched, MLP=16), tf32-rounded ----
            #pragma unroll
            for (int t = 0; t < TOK; t++) {
                const int id = __shfl_sync(0xffffffffu, cid, t);
                float4 e = ld4(emb + id * DD + f4);
                float4 ec;
                ec.x = __uint_as_float(tf32_bits(e.x));
                ec.y = __uint_as_float(tf32_bits(e.y));
                ec.z = __uint_as_float(tf32_bits(e.z));
                ec.w = __uint_as_float(tf32_bits(e.w));
                *(float4*)(xw + swx(t, f4)) = ec;
            }
            // ---- temporal branch: Linear(1->32) + LN + GELU per token ----
            #pragma unroll
            for (int t = 0; t < TOK; t++) {
                const float dn = __shfl_sync(0xffffffffu, cdt, t) * (1.0f / 1825.0f);
                const float v  = fmaf(dn, tpw, tpb);
                float s = v, q = v * v;
                warp_sum2(s, q);
                const float m  = s * (1.0f / TD);
                const float rs = rsqrtf(q * (1.0f / TD) - m * m + 1e-5f);
                const float u  = (v - m) * rs * tplw + tplb;
                xw[swx(t, DD + lane)] = __uint_as_float(tf32_bits(gelu_fast(u)));
            }
            __syncwarp();

            // ---- mm1: [16 x 160] @ [160 x 128]; 4x LDS.128 per 8-mma batch ----
            float D1[NNT][4];
            #pragma unroll
            for (int nt = 0; nt < NNT; nt++) { D1[nt][0]=0.f; D1[nt][1]=0.f; D1[nt][2]=0.f; D1[nt][3]=0.f; }

            for (int kt = 0; kt < NKT1; kt++) {
                const int k0 = kt * 8;
                const unsigned a0 = __float_as_uint(xw[swx(gid,     k0 + tig)]);
                const unsigned a1 = __float_as_uint(xw[swx(gid + 8, k0 + tig)]);
                const unsigned a2 = __float_as_uint(xw[swx(gid,     k0 + tig + 4)]);
                const unsigned a3 = __float_as_uint(xw[swx(gid + 8, k0 + tig + 4)]);
                #pragma unroll
                for (int h = 0; h < 2; h++) {
                    const uint4* base = wp1 + ((kt * 2 + h) * 4) * 32 + lane;
                    uint4 q0 = base[0], q1 = base[32], q2 = base[64], q3 = base[96];
                    mma8(D1[h*8+0], a0, a1, a2, a3, q0.x, q0.y);
                    mma8(D1[h*8+1], a0, a1, a2, a3, q0.z, q0.w);
                    mma8(D1[h*8+2], a0, a1, a2, a3, q1.x, q1.y);
                    mma8(D1[h*8+3], a0, a1, a2, a3, q1.z, q1.w);
                    mma8(D1[h*8+4], a0, a1, a2, a3, q2.x, q2.y);
                    mma8(D1[h*8+5], a0, a1, a2, a3, q2.z, q2.w);
                    mma8(D1[h*8+6], a0, a1, a2, a3, q3.x, q3.y);
                    mma8(D1[h*8+7], a0, a1, a2, a3, q3.z, q3.w);
                }
            }

            // ---- ep1: +bias, LN1 (stats on fragments), GELU, store tf32 back ----
            float s0 = 0.f, q0s = 0.f, s1 = 0.f, q1s = 0.f;
            #pragma unroll
            for (int nt = 0; nt < NNT; nt++) {
                const int c = nt * 8 + 2 * tig;
                const float2 bb = *(const float2*)(spar + c);
                D1[nt][0] += bb.x; D1[nt][1] += bb.y; D1[nt][2] += bb.x; D1[nt][3] += bb.y;
                s0 += D1[nt][0] + D1[nt][1]; q0s += D1[nt][0]*D1[nt][0] + D1[nt][1]*D1[nt][1];
                s1 += D1[nt][2] + D1[nt][3]; q1s += D1[nt][2]*D1[nt][2] + D1[nt][3]*D1[nt][3];
            }
            s0 = tig_sum(s0); q0s = tig_sum(q0s); s1 = tig_sum(s1); q1s = tig_sum(q1s);
            const float m0 = s0 * (1.0f / DD), rs0 = rsqrtf(q0s * (1.0f / DD) - m0 * m0 + 1e-5f);
            const float m1 = s1 * (1.0f / DD), rs1 = rsqrtf(q1s * (1.0f / DD) - m1 * m1 + 1e-5f);
            #pragma unroll
            for (int nt = 0; nt < NNT; nt++) {
                const int c = nt * 8 + 2 * tig;
                const float2 lw = *(const float2*)(spar + DD + c);
                const float2 lb = *(const float2*)(spar + 2 * DD + c);
                float g0 = gelu_fast((D1[nt][0] - m0) * rs0 * lw.x + lb.x);
                float g1 = gelu_fast((D1[nt][1] - m0) * rs0 * lw.y + lb.y);
                float g2 = gelu_fast((D1[nt][2] - m1) * rs1 * lw.x + lb.x);
                float g3 = gelu_fast((D1[nt][3] - m1) * rs1 * lw.y + lb.y);
                float2 v0, v1;
                v0.x = __uint_as_float(tf32_bits(g0)); v0.y = __uint_as_float(tf32_bits(g1));
                v1.x = __uint_as_float(tf32_bits(g2)); v1.y = __uint_as_float(tf32_bits(g3));
                *(float2*)(xw + swx(gid,     c)) = v0;
                *(float2*)(xw + swx(gid + 8, c)) = v1;
            }
            __syncwarp();

            // ---- mm2: A frags into registers, then 16 n-tiles ----
            unsigned A2[NKT2][4];
            #pragma unroll
            for (int kt = 0; kt < NKT2; kt++) {
                const int k0 = kt * 8;
                A2[kt][0] = __float_as_uint(xw[swx(gid,     k0 + tig)]);
                A2[kt][1] = __float_as_uint(xw[swx(gid + 8, k0 + tig)]);
                A2[kt][2] = __float_as_uint(xw[swx(gid,     k0 + tig + 4)]);
                A2[kt][3] = __float_as_uint(xw[swx(gid + 8, k0 + tig + 4)]);
            }
            __syncwarp();

            float s20 = 0.f, q20 = 0.f, s21 = 0.f, q21 = 0.f;
            for (int nt = 0; nt < NNT; nt++) {
                float D2[4] = {0.f, 0.f, 0.f, 0.f};
                #pragma unroll
                for (int h = 0; h < 2; h++) {
                    const uint4* base = wp2 + ((nt * 2 + h) * 4) * 32 + lane;
                    uint4 q0 = base[0], q1 = base[32], q2 = base[64], q3 = base[96];
                    const int kb = h * 8;
                    mma8(D2, A2[kb+0][0], A2[kb+0][1], A2[kb+0][2], A2[kb+0][3], q0.x, q0.y);
                    mma8(D2, A2[kb+1][0], A2[kb+1][1], A2[kb+1][2], A2[kb+1][3], q0.z, q0.w);
                    mma8(D2, A2[kb+2][0], A2[kb+2][1], A2[kb+2][2], A2[kb+2][3], q1.x, q1.y);
                    mma8(D2, A2[kb+3][0], A2[kb+3][1], A2[kb+3][2], A2[kb+3][3], q1.z, q1.w);
                    mma8(D2, A2[kb+4][0], A2[kb+4][1], A2[kb+4][2], A2[kb+4][3], q2.x, q2.y);
                    mma8(D2, A2[kb+5][0], A2[kb+5][1], A2[kb+5][2], A2[kb+5][3], q2.z, q2.w);
                    mma8(D2, A2[kb+6][0], A2[kb+6][1], A2[kb+6][2], A2[kb+6][3], q3.x, q3.y);
                    mma8(D2, A2[kb+7][0], A2[kb+7][1], A2[kb+7][2], A2[kb+7][3], q3.z, q3.w);
                }
                const int c = nt * 8 + 2 * tig;
                const float2 b2v = *(const float2*)(spar + 3 * DD + c);
                D2[0] += b2v.x; D2[1] += b2v.y; D2[2] += b2v.x; D2[3] += b2v.y;
                s20 += D2[0] + D2[1]; q20 += D2[0]*D2[0] + D2[1]*D2[1];
                s21 += D2[2] + D2[3]; q21 += D2[2]*D2[2] + D2[3]*D2[3];
                *(float2*)(xw + swx(gid,     c)) = make_float2(D2[0], D2[1]);
                *(float2*)(xw + swx(gid + 8, c)) = make_float2(D2[2], D2[3]);
            }
            s20 = tig_sum(s20); q20 = tig_sum(q20); s21 = tig_sum(s21); q21 = tig_sum(q21);
            const float mm0 = s20 * (1.0f / DD), rr0 = rsqrtf(q20 * (1.0f / DD) - mm0 * mm0 + 1e-5f);
            const float mm1v = s21 * (1.0f / DD), rr1 = rsqrtf(q21 * (1.0f / DD) - mm1v * mm1v + 1e-5f);
            __syncwarp();

            // ---- LN2 + masked pooling; stats broadcast via shfl ----
            #pragma unroll
            for (int t = 0; t < TOK; t++) {
                const float mt  = __shfl_sync(0xffffffffu, (t < 8) ? mm0 : mm1v, (t & 7) << 2);
                const float rst = __shfl_sync(0xffffffffu, (t < 8) ? rr0 : rr1,  (t & 7) << 2);
                if (l0 + t < len) {
                    const float4 v = ld4(xw + swx(t, f4));
                    pool.x += (v.x - mt) * rst * pl2w.x + pl2b.x;
                    pool.y += (v.y - mt) * rst * pl2w.y + pl2b.y;
                    pool.z += (v.z - mt) * rst * pl2w.z + pl2b.z;
                    pool.w += (v.w - mt) * rst * pl2w.w + pl2b.w;
                }
            }
            __syncwarp();
        }

        // ---- direct output: lane owns features f4..f4+3 of this row ----
        float4 o;
        if (len > 0) {
            const float inv = 1.0f / (float)len;
            o = make_float4(pool.x * inv, pool.y * inv, pool.z * inv, pool.w * inv);
        } else {
            o = make_float4(0.f, 0.f, 0.f, 0.f);
        }
        *(float4*)(out + row * DD + f4) = o;
    }
}

extern "C" void kernel_launch(void* const* d_in, const int* in_sizes, int n_in,
                              void* d_out, int out_size)
{
    const int*   ids     = (const int*)  d_in[0];
    const float* dates   = (const float*)d_in[1];
    const int*   lengths = (const int*)  d_in[2];
    const float* emb     = (const float*)d_in[3];
    const float* tp_w    = (const float*)d_in[4];
    const float* tp_b    = (const float*)d_in[5];
    const float* tp_lnw  = (const float*)d_in[6];
    const float* tp_lnb  = (const float*)d_in[7];
    const float* w1      = (const float*)d_in[8];
    const float* b1      = (const float*)d_in[9];
    const float* ln1w    = (const float*)d_in[10];
    const float* ln1b    = (const float*)d_in[11];
    const float* w2      = (const float*)d_in[12];
    const float* b2      = (const float*)d_in[13];
    const float* ln2w    = (const float*)d_in[14];
    const float* ln2b    = (const float*)d_in[15];
    float* out = (float*)d_out;

    const int B = in_sizes[2];            // 4096
    const int L = in_sizes[0] / B;        // 200

    pack_kernel<<<(QTOT + 255) / 256, 256>>>(w1, w2);   // also resets g_ctr

    const size_t smem_bytes = (size_t)QTOT * 16 + (size_t)(NW * TOK * 160 + 4 * DD) * sizeof(float);
    cudaFuncSetAttribute(tee_mma, cudaFuncAttributeMaxDynamicSharedMemorySize, (int)smem_bytes);
    tee_mma<<<GRID, BD, smem_bytes>>>(ids, dates, lengths, emb,
                                      tp_w, tp_b, tp_lnw, tp_lnb,
                                      b1, ln1w, ln1b, b2, ln2w, ln2b,
                                      out, B, L);
}